// round 12
// baseline (speedup 1.0000x reference)
#include <cuda_runtime.h>
#include <math.h>
#include <stdint.h>

#define BATCH 96
#define C 64
#define N 512
#define O 64
#define KM 10
#define KC 8
#define EPSBN 1e-5f

extern __shared__ char s_dyn[];

// ---------------- scratch -----------------------------------------------------
__device__ float g_xt [(size_t)2*BATCH*N*68];  // [task][b][p][64ch|norm|pad3] fp32
__device__ float g_cv [(size_t)BATCH*N*KM];    // task1 top-10 vals
__device__ int   g_ci [(size_t)BATCH*N*KM];    // task1 top-10 inds
__device__ int   g_fcnt[BATCH];
__device__ int   g_fq [BATCH*N];
__device__ float g_At0[BATCH*N*O];
__device__ float g_Dt0[BATCH*N*O];
__device__ float g_At1[BATCH*N*O];
__device__ float g_Dt1[BATCH*N*O];
__device__ int   g_idx [BATCH*N*KM];
__device__ int   g_idx8[BATCH*N*KC];
__device__ float g_em  [BATCH*N];
__device__ float g_xv  [BATCH*O];
__device__ float g_bv0 [BATCH*O];
__device__ float g_bv1 [BATCH*O];
__device__ float g_wAt [2][C*O];
__device__ float g_wDt [2][C*O];
__device__ float g_wS  [2][C*O];
__device__ float g_bias[2][O];

// ---------------- packed f32x2 ops ---------------------------------------------
__device__ __forceinline__ unsigned long long fma2(unsigned long long a,
                                                   unsigned long long b,
                                                   unsigned long long c) {
    unsigned long long d;
    asm("fma.rn.f32x2 %0, %1, %2, %3;" : "=l"(d) : "l"(a), "l"(b), "l"(c));
    return d;
}
__device__ __forceinline__ unsigned long long mul2(unsigned long long a,
                                                   unsigned long long b) {
    unsigned long long d;
    asm("mul.rn.f32x2 %0, %1, %2;" : "=l"(d) : "l"(a), "l"(b));
    return d;
}
__device__ __forceinline__ float2 unpk(unsigned long long a) {
    float2 r;
    asm("mov.b64 {%0,%1}, %2;" : "=f"(r.x), "=f"(r.y) : "l"(a));
    return r;
}

#define TOPK_INSERT(K, VV, II, dv, jv) do { \
    if ((dv) > VV[(K)-1]) { \
        VV[(K)-1] = (dv); II[(K)-1] = (jv); \
        _Pragma("unroll") \
        for (int s_ = (K)-1; s_ > 0; --s_) { \
            if (VV[s_] > VV[s_-1]) { \
                float tv_ = VV[s_]; VV[s_] = VV[s_-1]; VV[s_-1] = tv_; \
                int   ti_ = II[s_]; II[s_] = II[s_-1]; II[s_-1] = ti_; \
            } \
        } \
    } \
} while(0)

// ---------------- split/transpose prep: x -> [task][b][p][68] fp32 -------------
__global__ void k_split(const float* __restrict__ x, float* __restrict__ xt) {
    __shared__ float tile[64*65];
    int jc = blockIdx.x, b = blockIdx.y, sel = blockIdx.z;
    int bsrc = b;
    if (sel == 1) { int b0 = b/12, tt = b%12; int t2 = tt+1 > 11 ? 11 : tt+1; bsrc = b0*12 + t2; }
    const float* src = x + (size_t)bsrc*C*N + jc*64;
    int t = threadIdx.x;
    for (int e = t; e < 64*64; e += 256) {
        int c = e >> 6, jj = e & 63;
        tile[c*65 + jj] = src[c*N + jj];
    }
    __syncthreads();
    float* dst = xt + ((size_t)(sel*BATCH + b)*N + jc*64)*68;
    for (int u = t; u < 64*16; u += 256) {
        int p = u >> 4, ch = u & 15, c0 = ch*4;
        float4 v = make_float4(tile[(c0  )*65 + p], tile[(c0+1)*65 + p],
                               tile[(c0+2)*65 + p], tile[(c0+3)*65 + p]);
        *(float4*)(dst + p*68 + c0) = v;
    }
    if (t < 64) {
        float s = 0.f;
        #pragma unroll 8
        for (int c = 0; c < 64; ++c) { float v = tile[c*65 + t]; s += v*v; }
        *(float4*)(dst + t*68 + 64) = make_float4(s, 0.f, 0.f, 0.f);
    }
}

// ---------------- KNN dot body -----------------------------------------------------
__device__ __forceinline__ float knn_dot(const float* sp, const ulonglong2* q, int j) {
    const ulonglong2* p = (const ulonglong2*)(sp + j*68);
    unsigned long long a0=0ull, a1=0ull, a2=0ull, a3=0ull;
    #pragma unroll
    for (int u = 0; u < 16; u += 4) {
        ulonglong2 v0 = p[u], v1 = p[u+1], v2 = p[u+2], v3 = p[u+3];
        a0 = fma2(q[u].x,   v0.x, a0);
        a1 = fma2(q[u].y,   v0.y, a1);
        a2 = fma2(q[u+1].x, v1.x, a2);
        a3 = fma2(q[u+1].y, v1.y, a3);
        a0 = fma2(q[u+2].x, v2.x, a0);
        a1 = fma2(q[u+2].y, v2.y, a1);
        a2 = fma2(q[u+3].x, v3.x, a2);
        a3 = fma2(q[u+3].y, v3.y, a3);
    }
    float n0 = sp[j*68 + 64];
    float2 f0 = unpk(a0), f1 = unpk(a1), f2 = unpk(a2), f3 = unpk(a3);
    return (((f0.x + f0.y) + (f1.x + f1.y))
          + ((f2.x + f2.y) + (f3.x + f3.y))) - n0;
}
__device__ __forceinline__ void load_query2(const float* sp, int i, ulonglong2* q) {
    unsigned long long two;
    asm("mov.b64 %0, {%1,%1};" : "=l"(two) : "f"(2.0f));
    const ulonglong2* qp = (const ulonglong2*)(sp + i*68);
    #pragma unroll
    for (int u = 0; u < 16; ++u) {
        ulonglong2 v = qp[u];
        q[u].x = mul2(v.x, two);
        q[u].y = mul2(v.y, two);
    }
}

// ---------------- KNN: 256 queries/block, both tasks K10 ---------------------------
#define KNN_SMEM_BYTES (N*68*4)

__global__ __launch_bounds__(256, 1)
void knn3(const float4* __restrict__ xt, int* __restrict__ idx10,
          int* __restrict__ idx8, float* __restrict__ cv, int* __restrict__ ci) {
    const int t = threadIdx.x;
    const int bid = blockIdx.x;
    const int chunk = bid & 1;
    const int r = bid >> 1;
    const int b = r % BATCH;
    const int task = r / BATCH;

    const float4* src = xt + ((size_t)(task*BATCH + b))*N*17;
    float* sp = (float*)s_dyn;
    float4* spv = (float4*)s_dyn;
    for (int e = t; e < N*17; e += 256) spv[e] = src[e];
    __syncthreads();

    const int i = chunk*256 + t;
    ulonglong2 q[16];
    load_query2(sp, i, q);

    float vals[KM]; int inds[KM];
    #pragma unroll
    for (int s = 0; s < KM; ++s) { vals[s] = -INFINITY; inds[s] = 0; }
    for (int j = 0; j < N; ++j) {
        float d = knn_dot(sp, q, j);
        TOPK_INSERT(KM, vals, inds, d, j);
    }

    if (task == 0) {
        int* o = idx10 + ((size_t)b*N + i)*KM;
        #pragma unroll
        for (int s = 0; s < KM; ++s) o[s] = inds[s];
    } else {
        int* o = idx8 + ((size_t)b*N + i)*KC;
        #pragma unroll
        for (int s = 0; s < KC; ++s) o[s] = inds[s];
        size_t base = ((size_t)b*N + i)*KM;
        #pragma unroll
        for (int s = 0; s < KM; ++s) { cv[base+s] = vals[s]; ci[base+s] = inds[s]; }
    }
}

// ---------------- patch: clean queries from cache; flag dirty ones ------------------
__global__ __launch_bounds__(512, 1)
void k_patch(const float* __restrict__ em, const float* __restrict__ cv,
             const int* __restrict__ ci, int* __restrict__ idx_out,
             int* __restrict__ fcnt, int* __restrict__ fq) {
    __shared__ float sem[N];
    __shared__ int sM[16];
    __shared__ int snM;
    __shared__ int scnt;
    int b = blockIdx.x, t = threadIdx.x;
    sem[t] = em[b*N + t];
    if (t == 0) scnt = 0;
    __syncthreads();
    if (t == 0) {
        int n = 0;
        for (int j = 0; j < N; ++j)
            if (sem[j] == 0.f && n < 16) sM[n++] = j;
        snM = n;
    }
    __syncthreads();
    bool need;
    if (sem[t] == 0.f) need = true;
    else {
        size_t base = ((size_t)b*N + t)*KM;
        float v[KM]; int id[KM]; int mcnt = 0;
        #pragma unroll
        for (int s = 0; s < KM; ++s) {
            v[s] = cv[base+s]; id[s] = ci[base+s];
            mcnt += (sem[id[s]] == 0.f) ? 1 : 0;
        }
        need = (mcnt > 0);
        if (!need) {
            float vals[KM]; int inds[KM];
            #pragma unroll
            for (int s = 0; s < KM; ++s) { vals[s] = -INFINITY; inds[s] = 0; }
            int nM = snM;
            for (int m = 0; m < nM; ++m) TOPK_INSERT(KM, vals, inds, 0.f, sM[m]);
            #pragma unroll
            for (int s = 0; s < KM; ++s) TOPK_INSERT(KM, vals, inds, v[s], id[s]);
            int* o = idx_out + ((size_t)b*N + t)*KM;
            #pragma unroll
            for (int s = 0; s < KM; ++s) o[s] = inds[s];
        }
    }
    if (need) { int pos = atomicAdd(&scnt, 1); fq[b*N + pos] = t; }
    __syncthreads();
    if (t == 0) fcnt[b] = scnt;
}

// ---------------- selective rescan (dirty queries, 4 threads/query) -----------------
#define RS_SMEM (N*68*4 + 2048 + 128*4*KM*4*2 + 64)
__global__ __launch_bounds__(512, 1)
void k_rescan(const float4* __restrict__ xt, const float* __restrict__ em,
              const int* __restrict__ fcnt, const int* __restrict__ fq,
              int* __restrict__ idx_out) {
    int b = blockIdx.x, t = threadIdx.x;
    float* sp   = (float*)s_dyn;
    int*   sqid = (int*)(s_dyn + N*68*4);
    float* sv4  = (float*)(s_dyn + N*68*4 + 2048);
    int*   si4  = (int*)(s_dyn + N*68*4 + 2048 + 128*4*KM*4);

    const float4* src = xt + ((size_t)(BATCH + b))*N*17;
    float4* spv = (float4*)sp;
    for (int e = t; e < N*17; e += 512) {
        int p = e / 17;
        float4 v = src[e];
        if (em[b*N + p] == 0.f) v = make_float4(0.f,0.f,0.f,0.f);
        spv[e] = v;
    }
    int cnt = fcnt[b];
    for (int e = t; e < cnt; e += 512) sqid[e] = fq[b*N + e];
    __syncthreads();

    for (int base = 0; base < cnt; base += 128) {
        int qi = base + (t >> 2), part = t & 3;
        float vals[KM]; int inds[KM];
        #pragma unroll
        for (int s = 0; s < KM; ++s) { vals[s] = -INFINITY; inds[s] = 0; }
        if (qi < cnt) {
            int qq = sqid[qi];
            ulonglong2 q[16];
            load_query2(sp, qq, q);
            const int j0 = part*128;
            for (int j = j0; j < j0 + 128; ++j) {
                float d = knn_dot(sp, q, j);
                TOPK_INSERT(KM, vals, inds, d, j);
            }
        }
        int lq = t >> 2;
        #pragma unroll
        for (int s = 0; s < KM; ++s) {
            sv4[(lq*4 + part)*KM + s] = vals[s];
            si4[(lq*4 + part)*KM + s] = inds[s];
        }
        __syncthreads();
        if (t < 128 && base + t < cnt) {
            float v2[KM]; int i2[KM];
            #pragma unroll
            for (int s = 0; s < KM; ++s) { v2[s] = -INFINITY; i2[s] = 0; }
            for (int part2 = 0; part2 < 4; ++part2)
                #pragma unroll
                for (int s = 0; s < KM; ++s) {
                    float vv = sv4[(t*4 + part2)*KM + s];
                    int   ii = si4[(t*4 + part2)*KM + s];
                    TOPK_INSERT(KM, v2, i2, vv, ii);
                }
            int qq = sqid[base + t];
            int* o = idx_out + ((size_t)b*N + qq)*KM;
            #pragma unroll
            for (int s = 0; s < KM; ++s) o[s] = i2[s];
        }
        __syncthreads();
    }
}

// ---------------- weight prep ---------------------------------------------------
__global__ void k_prep_w(const float* __restrict__ w, const float* __restrict__ g,
                         const float* __restrict__ bb, const float* __restrict__ m,
                         const float* __restrict__ v,
                         float* __restrict__ wAt, float* __restrict__ wDt,
                         float* __restrict__ wS, float* __restrict__ bias) {
    int e = blockIdx.x*blockDim.x + threadIdx.x;
    if (e >= C*O) return;
    int o = e & 63, c = e >> 6;
    float s = g[o] / sqrtf(v[o] + EPSBN);
    float wa = w[o*128 + c]      * s;
    float wc = w[o*128 + 64 + c] * s;
    wAt[c*O + o] = wa;
    wDt[c*O + o] = wc - wa;
    wS [c*O + o] = wc;
    if (c == 0) bias[o] = bb[o] - m[o]*s;
}

// ---------------- stage1: mean + erasevec + biasvec0 ------------------------------
__global__ void k_stage1(const float* __restrict__ x,
                         const float* __restrict__ we, const float* __restrict__ be,
                         const float* __restrict__ ge, const float* __restrict__ bee,
                         const float* __restrict__ me, const float* __restrict__ ve,
                         const float* __restrict__ wS0, const float* __restrict__ bias0,
                         float* __restrict__ bv0) {
    __shared__ float sres[64], syv[64];
    int b = blockIdx.x, t = threadIdx.x;
    int w = t >> 5, l = t & 31;
    #pragma unroll
    for (int u = 0; u < 4; ++u) {
        int c = w*4 + u;
        const float* p = x + ((size_t)b*C + c)*N;
        float s = 0.f;
        #pragma unroll
        for (int n0 = 0; n0 < 16; ++n0) s += p[n0*32 + l];
        #pragma unroll
        for (int off = 16; off > 0; off >>= 1) s += __shfl_down_sync(~0u, s, off);
        if (l == 0) sres[c] = s * (1.f/N);
    }
    __syncthreads();
    if (t < 64) {
        float a = 0.f;
        #pragma unroll 8
        for (int cc = 0; cc < C; ++cc) a += we[t*C + cc]*sres[cc];
        a += be[t];
        float sc = ge[t] / sqrtf(ve[t] + EPSBN);
        syv[t] = (a - me[t])*sc + bee[t];
    }
    __syncthreads();
    if (t < 64) {
        float a = bias0[t];
        #pragma unroll 8
        for (int cc = 0; cc < C; ++cc) a += wS0[cc*O + t]*syv[cc];
        bv0[b*O + t] = a;
    }
}

// ---------------- A/D GEMMs --------------------------------------------------------
__global__ void k_gemm(const float* __restrict__ x, const float* __restrict__ wAt,
                       const float* __restrict__ wDt,
                       float* __restrict__ At, float* __restrict__ Dt, int remap) {
    __shared__ float xs [C*64];
    __shared__ float swA[C*O];
    __shared__ float swD[C*O];
    int b = blockIdx.y, jc = blockIdx.x;
    int bsrc = b;
    if (remap) { int b0 = b/12, tt = b%12; int t2 = tt+1 > 11 ? 11 : tt+1; bsrc = b0*12 + t2; }
    int t = threadIdx.x;
    for (int e = t; e < C*O; e += 256) { swA[e] = wAt[e]; swD[e] = wDt[e]; }
    const float* xb = x + (size_t)bsrc*C*N + jc*64;
    for (int e = t; e < C*64; e += 256) {
        int c = e >> 6, jj = e & 63;
        xs[c*64 + jj] = xb[c*N + jj];
    }
    __syncthreads();
    int og = t & 15, jt = t >> 4;
    float a[4][4] = {}, d[4][4] = {};
    #pragma unroll 4
    for (int c = 0; c < C; ++c) {
        float4 wa = *(const float4*)(swA + c*O + og*4);
        float4 wd = *(const float4*)(swD + c*O + og*4);
        float4 xv = *(const float4*)(xs  + c*64 + jt*4);
        float xw[4]  = {xv.x, xv.y, xv.z, xv.w};
        float wav[4] = {wa.x, wa.y, wa.z, wa.w};
        float wdv[4] = {wd.x, wd.y, wd.z, wd.w};
        #pragma unroll
        for (int oo = 0; oo < 4; ++oo)
            #pragma unroll
            for (int jj = 0; jj < 4; ++jj) {
                a[oo][jj] += wav[oo]*xw[jj];
                d[oo][jj] += wdv[oo]*xw[jj];
            }
    }
    int jbase = jc*64 + jt*4;
    #pragma unroll
    for (int jj = 0; jj < 4; ++jj) {
        float4 va = make_float4(a[0][jj], a[1][jj], a[2][jj], a[3][jj]);
        float4 vd = make_float4(d[0][jj], d[1][jj], d[2][jj], d[3][jj]);
        *(float4*)(At + ((size_t)b*N + jbase + jj)*O + og*4) = va;
        *(float4*)(Dt + ((size_t)b*N + jbase + jj)*O + og*4) = vd;
    }
}

// ---------------- edge pool + n-pool fused -------------------------------------------
#define EP_SMEM_BYTES (N*O*4 + N*KM*4 + N*4 + 16*64*4*2)
template<bool HAS_EM>
__global__ __launch_bounds__(512, 1)
void k_edgepool(const float* __restrict__ At, const float* __restrict__ Dt,
                const int* __restrict__ idx, const float* __restrict__ em,
                const float* __restrict__ bvec, float* __restrict__ out,
                float* __restrict__ xv, int add) {
    float* sA   = (float*)s_dyn;                          // [512][64]
    int*   sI   = (int*)(s_dyn + N*O*4);                  // [512][10]
    float* sEm  = (float*)(s_dyn + N*O*4 + N*KM*4);       // [512]
    float* rmax = sEm + N;                                // [16][64]
    float* rsum = rmax + 16*64;                           // [16][64]
    int b = blockIdx.x, t = threadIdx.x;
    {
        const float4* src = (const float4*)(At + (size_t)b*N*O);
        float4* dst = (float4*)sA;
        for (int e = t; e < N*O/4; e += 512) dst[e] = src[e];
        const int* isrc = idx + (size_t)b*N*KM;
        for (int e = t; e < N*KM; e += 512) sI[e] = isrc[e];
        if (HAS_EM) sEm[t] = em[b*N + t];
    }
    __syncthreads();
    int w = t >> 5, l = t & 31;
    float2 bv = *(const float2*)(bvec + b*O + 2*l);
    float2 tmax = make_float2(-INFINITY, -INFINITY);
    float2 tsum = make_float2(0.f, 0.f);
    for (int ii = 0; ii < 32; ++ii) {
        int i = w*32 + ii;
        float2 mx = make_float2(-INFINITY, -INFINITY);
        #pragma unroll
        for (int k = 0; k < KM; ++k) {
            int jk = sI[i*KM + k];
            float2 v = *(const float2*)(sA + jk*O + 2*l);
            if (HAS_EM) { float e = sEm[jk]; v.x *= e; v.y *= e; }
            mx.x = fmaxf(mx.x, v.x); mx.y = fmaxf(mx.y, v.y);
        }
        float ei = HAS_EM ? sEm[i] : 1.f;
        float2 dt = *(const float2*)(Dt + ((size_t)b*N + i)*O + 2*l);
        float vx = mx.x + ei*dt.x + bv.x;
        float vy = mx.y + ei*dt.y + bv.y;
        vx = vx > 0.f ? vx : 0.2f*vx;
        vy = vy > 0.f ? vy : 0.2f*vy;
        tmax.x = fmaxf(tmax.x, vx); tmax.y = fmaxf(tmax.y, vy);
        tsum.x += vx;               tsum.y += vy;
    }
    *(float2*)(rmax + w*64 + 2*l) = tmax;
    *(float2*)(rsum + w*64 + 2*l) = tsum;
    __syncthreads();
    if (t < 64) {
        float m = -INFINITY, s2 = 0.f;
        #pragma unroll
        for (int wi2 = 0; wi2 < 16; ++wi2) {
            m  = fmaxf(m, rmax[wi2*64 + t]);
            s2 += rsum[wi2*64 + t];
        }
        float mean = s2 * (1.f/N);
        if (add) { out[b*128 + t] += m; out[b*128 + 64 + t] += mean; }
        else     { out[b*128 + t]  = m; out[b*128 + 64 + t]  = mean;
                   if (xv) xv[b*O + t] = m; }
    }
}

// ---------------- stage2 (fused correlation + erase-vec) ---------------------------------
__global__ __launch_bounds__(512, 1)
void k_stage2(const float* __restrict__ xv, const float* __restrict__ wr,
              const float* __restrict__ x, const int* __restrict__ idx8,
              const float* __restrict__ we, const float* __restrict__ be,
              const float* __restrict__ ge, const float* __restrict__ bee,
              const float* __restrict__ me, const float* __restrict__ ve,
              const float* __restrict__ wS1, const float* __restrict__ bias1,
              float* __restrict__ em_out, float* __restrict__ bv1) {
    __shared__ float sxv[64], sq[64], sres[64], syv[64];
    __shared__ float sf[512], sem[512], ssm[512], sred[512];
    __shared__ float sv[512];
    __shared__ int   si[512];
    int b = blockIdx.x, t = threadIdx.x;
    int b0 = b/12, tt2 = b%12; int t2 = tt2+1 > 11 ? 11 : tt2+1;
    const float* x1b = x + (size_t)(b0*12 + t2)*C*N;

    if (t < 64) sxv[t] = xv[b*O + t];
    __syncthreads();
    if (t < 64) {
        float a = 0.f;
        #pragma unroll 8
        for (int c = 0; c < C; ++c) a += wr[t*C + c]*sxv[c];
        sq[t] = a;
    }
    __syncthreads();
    {
        float a = 0.f;
        const float* p = x1b + t;
        #pragma unroll 8
        for (int c = 0; c < C; ++c) a += sq[c]*p[c*N];
        sf[t] = a * 0.125f;
    }
    __syncthreads();
    {
        float fk = sf[t];
        const int* ip = idx8 + ((size_t)b*N + t)*KC;
        #pragma unroll
        for (int k = 0; k < KC; ++k) fk += sf[ip[k]];
        sv[t] = fk; si[t] = t;
    }
    __syncthreads();
    for (int s = 256; s > 0; s >>= 1) {
        if (t < s) {
            float v2 = sv[t+s]; int i2 = si[t+s];
            if (v2 > sv[t] || (v2 == sv[t] && i2 < si[t])) { sv[t] = v2; si[t] = i2; }
        }
        __syncthreads();
    }
    int index = si[0];
    sem[t] = 1.f;
    __syncthreads();
    if (t < KC) sem[idx8[((size_t)b*N + index)*KC + t]] = 0.f;
    if (t == KC) sem[index] = 0.f;
    __syncthreads();
    float s_ = sf[t] - (1.f - sem[t])*1e8f;
    sred[t] = s_;
    __syncthreads();
    for (int st = 256; st > 0; st >>= 1) {
        if (t < st) sred[t] = fmaxf(sred[t], sred[t+st]);
        __syncthreads();
    }
    float mxv = sred[0];
    __syncthreads();
    float e = expf(s_ - mxv);
    sred[t] = e;
    __syncthreads();
    for (int st = 256; st > 0; st >>= 1) {
        if (t < st) sred[t] += sred[t+st];
        __syncthreads();
    }
    float ssum = sred[0];
    __syncthreads();
    ssm[t] = e / ssum;
    __syncthreads();
    {
        int w = t >> 5, l = t & 31;
        #pragma unroll
        for (int u = 0; u < 4; ++u) {
            int c = w*4 + u;
            const float* p = x1b + (size_t)c*N;
            float s = 0.f;
            #pragma unroll
            for (int n0 = 0; n0 < 16; ++n0) { int n = n0*32 + l; s += p[n]*ssm[n]; }
            #pragma unroll
            for (int off = 16; off > 0; off >>= 1) s += __shfl_down_sync(~0u, s, off);
            if (l == 0) sres[c] = s;
        }
    }
    __syncthreads();
    if (t < 64) {
        float a = 0.f;
        #pragma unroll 8
        for (int c = 0; c < C; ++c) a += we[t*C + c]*sres[c];
        a += be[t];
        float sc = ge[t] / sqrtf(ve[t] + EPSBN);
        syv[t] = (a - me[t])*sc + bee[t];
    }
    __syncthreads();
    if (t < 64) {
        float a = bias1[t];
        #pragma unroll 8
        for (int c = 0; c < C; ++c) a += wS1[c*O + t]*syv[c];
        bv1[b*O + t] = a;
    }
    em_out[b*N + t] = sem[t];
}

// =============================================================================
extern "C" void kernel_launch(void* const* d_in, const int* in_sizes, int n_in,
                              void* d_out, int out_size) {
    const float* x        = (const float*)d_in[0];
    const float* w_reduce = (const float*)d_in[1];
    const float* w_erase  = (const float*)d_in[2];
    const float* b_erase  = (const float*)d_in[3];
    const float* g_erase  = (const float*)d_in[4];
    const float* be_erase = (const float*)d_in[5];
    const float* m_erase  = (const float*)d_in[6];
    const float* v_erase  = (const float*)d_in[7];
    const float* w0 = (const float*)d_in[8];
    const float* g0 = (const float*)d_in[9];
    const float* b0 = (const float*)d_in[10];
    const float* m0 = (const float*)d_in[11];
    const float* v0 = (const float*)d_in[12];
    const float* w1 = (const float*)d_in[13];
    const float* g1 = (const float*)d_in[14];
    const float* b1 = (const float*)d_in[15];
    const float* m1 = (const float*)d_in[16];
    const float* v1 = (const float*)d_in[17];
    float* out = (float*)d_out;

    float *p_xt, *p_cv, *p_At0, *p_Dt0, *p_At1, *p_Dt1;
    float *p_em, *p_xv, *p_bv0, *p_bv1, *p_wAt, *p_wDt, *p_wS, *p_bias;
    int *p_ci, *p_idx, *p_idx8, *p_fcnt, *p_fq;
    cudaGetSymbolAddress((void**)&p_xt,  g_xt);
    cudaGetSymbolAddress((void**)&p_cv,  g_cv);
    cudaGetSymbolAddress((void**)&p_ci,  g_ci);
    cudaGetSymbolAddress((void**)&p_fcnt,g_fcnt);
    cudaGetSymbolAddress((void**)&p_fq,  g_fq);
    cudaGetSymbolAddress((void**)&p_At0, g_At0);
    cudaGetSymbolAddress((void**)&p_Dt0, g_Dt0);
    cudaGetSymbolAddress((void**)&p_At1, g_At1);
    cudaGetSymbolAddress((void**)&p_Dt1, g_Dt1);
    cudaGetSymbolAddress((void**)&p_em,  g_em);
    cudaGetSymbolAddress((void**)&p_xv,  g_xv);
    cudaGetSymbolAddress((void**)&p_bv0, g_bv0);
    cudaGetSymbolAddress((void**)&p_bv1, g_bv1);
    cudaGetSymbolAddress((void**)&p_wAt, g_wAt);
    cudaGetSymbolAddress((void**)&p_wDt, g_wDt);
    cudaGetSymbolAddress((void**)&p_wS,  g_wS);
    cudaGetSymbolAddress((void**)&p_bias,g_bias);
    cudaGetSymbolAddress((void**)&p_idx, g_idx);
    cudaGetSymbolAddress((void**)&p_idx8,g_idx8);

    cudaFuncSetAttribute((const void*)knn3,     cudaFuncAttributeMaxDynamicSharedMemorySize, KNN_SMEM_BYTES);
    cudaFuncSetAttribute((const void*)k_rescan, cudaFuncAttributeMaxDynamicSharedMemorySize, RS_SMEM);
    cudaFuncSetAttribute((const void*)k_edgepool<false>, cudaFuncAttributeMaxDynamicSharedMemorySize, EP_SMEM_BYTES);
    cudaFuncSetAttribute((const void*)k_edgepool<true>,  cudaFuncAttributeMaxDynamicSharedMemorySize, EP_SMEM_BYTES);

    k_prep_w<<<16, 256>>>(w0, g0, b0, m0, v0, p_wAt,       p_wDt,       p_wS,       p_bias);
    k_prep_w<<<16, 256>>>(w1, g1, b1, m1, v1, p_wAt + C*O, p_wDt + C*O, p_wS + C*O, p_bias + O);

    k_split<<<dim3(8, BATCH, 2), 256>>>(x, p_xt);

    // fused dual KNN: task0 -> idx10 (k=10), task1 -> idx8 (k=8) + top-10 cache
    knn3<<<2*2*BATCH, 256, KNN_SMEM_BYTES>>>((const float4*)p_xt, p_idx, p_idx8, p_cv, p_ci);

    k_stage1<<<BATCH, 512>>>(x, w_erase, b_erase, g_erase, be_erase, m_erase, v_erase,
                             p_wS, p_bias, p_bv0);

    k_gemm<<<dim3(8, BATCH), 256>>>(x, p_wAt,       p_wDt,       p_At0, p_Dt0, 0);
    k_gemm<<<dim3(8, BATCH), 256>>>(x, p_wAt + C*O, p_wDt + C*O, p_At1, p_Dt1, 1);

    // branch 0 (edgepool + n-pool fused)
    k_edgepool<false><<<BATCH, 512, EP_SMEM_BYTES>>>(p_At0, p_Dt0, p_idx, nullptr, p_bv0,
                                                     out, p_xv, 0);

    // correlation / erase #2
    k_stage2<<<BATCH, 512>>>(p_xv, w_reduce, x, p_idx8,
                             w_erase, b_erase, g_erase, be_erase, m_erase, v_erase,
                             p_wS + C*O, p_bias + O, p_em, p_bv1);

    // branch-1 knn: clean queries from cache, dirty ones via selective rescan
    k_patch<<<BATCH, 512>>>(p_em, p_cv, p_ci, p_idx, p_fcnt, p_fq);
    k_rescan<<<BATCH, 512, RS_SMEM>>>((const float4*)p_xt, p_em, p_fcnt, p_fq, p_idx);

    // branch 1
    k_edgepool<true><<<BATCH, 512, EP_SMEM_BYTES>>>(p_At1, p_Dt1, p_idx, p_em, p_bv1,
                                                    out, nullptr, 1);
}

// round 13
// speedup vs baseline: 2.2388x; 2.2388x over previous
#include <cuda_runtime.h>
#include <math.h>
#include <stdint.h>

#define BATCH 96
#define C 64
#define N 512
#define O 64
#define KM 10
#define KC 8
#define K19 19
#define EPSBN 1e-5f

extern __shared__ char s_dyn[];

__device__ __forceinline__ int srcmap(int b) {
    int b0 = b/12, tt = b%12;
    int t2 = tt+1 > 11 ? 11 : tt+1;
    return b0*12 + t2;
}

// ---------------- scratch -----------------------------------------------------
__device__ float g_xt [(size_t)BATCH*N*68];   // [b][p][64ch|norm|pad3] fp32
__device__ float g_cv [(size_t)BATCH*N*K19];  // per-b top-19 vals
__device__ int   g_ci [(size_t)BATCH*N*K19];  // per-b top-19 inds
__device__ float g_At0[BATCH*N*O];
__device__ float g_Dt0[BATCH*N*O];
__device__ float g_At1[BATCH*N*O];
__device__ float g_Dt1[BATCH*N*O];
__device__ int   g_idx [BATCH*N*KM];          // branch-1 knn (patch output)
__device__ float g_em  [BATCH*N];
__device__ float g_xv  [BATCH*O];
__device__ float g_bv0 [BATCH*O];
__device__ float g_bv1 [BATCH*O];
__device__ float g_wAt [2][C*O];
__device__ float g_wDt [2][C*O];
__device__ float g_wS  [2][C*O];
__device__ float g_bias[2][O];

// ---------------- packed f32x2 ops ---------------------------------------------
__device__ __forceinline__ unsigned long long fma2(unsigned long long a,
                                                   unsigned long long b,
                                                   unsigned long long c) {
    unsigned long long d;
    asm("fma.rn.f32x2 %0, %1, %2, %3;" : "=l"(d) : "l"(a), "l"(b), "l"(c));
    return d;
}
__device__ __forceinline__ unsigned long long mul2(unsigned long long a,
                                                   unsigned long long b) {
    unsigned long long d;
    asm("mul.rn.f32x2 %0, %1, %2;" : "=l"(d) : "l"(a), "l"(b));
    return d;
}
__device__ __forceinline__ float2 unpk(unsigned long long a) {
    float2 r;
    asm("mov.b64 {%0,%1}, %2;" : "=f"(r.x), "=f"(r.y) : "l"(a));
    return r;
}

#define TOPK_INSERT(K, VV, II, dv, jv) do { \
    if ((dv) > VV[(K)-1]) { \
        VV[(K)-1] = (dv); II[(K)-1] = (jv); \
        _Pragma("unroll") \
        for (int s_ = (K)-1; s_ > 0; --s_) { \
            if (VV[s_] > VV[s_-1]) { \
                float tv_ = VV[s_]; VV[s_] = VV[s_-1]; VV[s_-1] = tv_; \
                int   ti_ = II[s_]; II[s_] = II[s_-1]; II[s_-1] = ti_; \
            } \
        } \
    } \
} while(0)

// ---------------- split/transpose prep: x -> [b][p][68] fp32 --------------------
__global__ void k_split(const float* __restrict__ x, float* __restrict__ xt) {
    __shared__ float tile[64*65];
    int jc = blockIdx.x, b = blockIdx.y;
    const float* src = x + (size_t)b*C*N + jc*64;
    int t = threadIdx.x;
    for (int e = t; e < 64*64; e += 256) {
        int c = e >> 6, jj = e & 63;
        tile[c*65 + jj] = src[c*N + jj];
    }
    __syncthreads();
    float* dst = xt + ((size_t)b*N + jc*64)*68;
    for (int u = t; u < 64*16; u += 256) {
        int p = u >> 4, ch = u & 15, c0 = ch*4;
        float4 v = make_float4(tile[(c0  )*65 + p], tile[(c0+1)*65 + p],
                               tile[(c0+2)*65 + p], tile[(c0+3)*65 + p]);
        *(float4*)(dst + p*68 + c0) = v;
    }
    if (t < 64) {
        float s = 0.f;
        #pragma unroll 8
        for (int c = 0; c < 64; ++c) { float v = tile[c*65 + t]; s += v*v; }
        *(float4*)(dst + t*68 + 64) = make_float4(s, 0.f, 0.f, 0.f);
    }
}

// ---------------- KNN: one K19 scan per unique point set -------------------------
#define KNN_SMEM_BYTES (N*68*4)

__global__ __launch_bounds__(256, 1)
void knn19(const float4* __restrict__ xt, float* __restrict__ cv, int* __restrict__ ci) {
    const int t = threadIdx.x;
    const int b = blockIdx.x >> 1;
    const int chunk = blockIdx.x & 1;

    const float4* src = xt + (size_t)b*N*17;
    float* sp = (float*)s_dyn;
    float4* spv = (float4*)s_dyn;
    for (int e = t; e < N*17; e += 256) spv[e] = src[e];
    __syncthreads();

    const int i = chunk*256 + t;
    ulonglong2 q[16];
    {
        unsigned long long two;
        asm("mov.b64 %0, {%1,%1};" : "=l"(two) : "f"(2.0f));
        const ulonglong2* qp = (const ulonglong2*)(sp + i*68);
        #pragma unroll
        for (int u = 0; u < 16; ++u) {
            ulonglong2 v = qp[u];
            q[u].x = mul2(v.x, two);
            q[u].y = mul2(v.y, two);
        }
    }

    float vals[K19]; int inds[K19];
    #pragma unroll
    for (int s = 0; s < K19; ++s) { vals[s] = -INFINITY; inds[s] = 0; }
    for (int j = 0; j < N; ++j) {
        const ulonglong2* p = (const ulonglong2*)(sp + j*68);
        unsigned long long a0=0ull, a1=0ull, a2=0ull, a3=0ull;
        #pragma unroll
        for (int u = 0; u < 16; u += 4) {
            ulonglong2 v0 = p[u], v1 = p[u+1], v2 = p[u+2], v3 = p[u+3];
            a0 = fma2(q[u].x,   v0.x, a0);
            a1 = fma2(q[u].y,   v0.y, a1);
            a2 = fma2(q[u+1].x, v1.x, a2);
            a3 = fma2(q[u+1].y, v1.y, a3);
            a0 = fma2(q[u+2].x, v2.x, a0);
            a1 = fma2(q[u+2].y, v2.y, a1);
            a2 = fma2(q[u+3].x, v3.x, a2);
            a3 = fma2(q[u+3].y, v3.y, a3);
        }
        float n0 = sp[j*68 + 64];
        float2 f0 = unpk(a0), f1 = unpk(a1), f2 = unpk(a2), f3 = unpk(a3);
        float d = (((f0.x + f0.y) + (f1.x + f1.y))
                 + ((f2.x + f2.y) + (f3.x + f3.y))) - n0;
        TOPK_INSERT(K19, vals, inds, d, j);
    }
    size_t base = ((size_t)b*N + i)*K19;
    #pragma unroll
    for (int s = 0; s < K19; ++s) { cv[base+s] = vals[s]; ci[base+s] = inds[s]; }
}

// ---------------- patch: branch-1 knn from cached top-19 + mask -------------------
__global__ __launch_bounds__(512, 1)
void k_patch(const float* __restrict__ xt, const float* __restrict__ em,
             const float* __restrict__ cv, const int* __restrict__ ci,
             int* __restrict__ idx_out) {
    __shared__ float sem[N];
    __shared__ float snm[N];
    __shared__ int   sM[16];
    __shared__ int   snM;
    __shared__ float wv[32*KM];
    __shared__ int   wi[32*KM];
    __shared__ float gvv[KM];
    __shared__ int   gii[KM];
    int b = blockIdx.x, t = threadIdx.x;
    int src = srcmap(b);
    sem[t] = em[b*N + t];
    snm[t] = xt[((size_t)src*N + t)*68 + 64];
    __syncthreads();
    if (t == 0) {
        int n = 0;
        for (int j = 0; j < N; ++j)
            if (sem[j] == 0.f && n < 16) sM[n++] = j;
        snM = n;
    }
    if (t < 32) {
        float v[KM]; int id[KM];
        #pragma unroll
        for (int s = 0; s < KM; ++s) { v[s] = -INFINITY; id[s] = 0; }
        for (int e = 0; e < 16; ++e) {
            int j = t*16 + e;
            if (sem[j] != 0.f) { float d = -snm[j]; TOPK_INSERT(KM, v, id, d, j); }
        }
        #pragma unroll
        for (int s = 0; s < KM; ++s) { wv[t*KM + s] = v[s]; wi[t*KM + s] = id[s]; }
    }
    __syncthreads();
    if (t == 0) {
        float v[KM]; int id[KM];
        #pragma unroll
        for (int s = 0; s < KM; ++s) { v[s] = -INFINITY; id[s] = 0; }
        for (int l = 0; l < 32; ++l)
            for (int s = 0; s < KM; ++s) {
                float vv = wv[l*KM + s]; int ii = wi[l*KM + s];
                TOPK_INSERT(KM, v, id, vv, ii);
            }
        #pragma unroll
        for (int s = 0; s < KM; ++s) { gvv[s] = v[s]; gii[s] = id[s]; }
    }
    __syncthreads();

    float vals[KM]; int inds[KM];
    #pragma unroll
    for (int s = 0; s < KM; ++s) { vals[s] = -INFINITY; inds[s] = 0; }
    int nM = snM;
    for (int m = 0; m < nM; ++m) TOPK_INSERT(KM, vals, inds, 0.f, sM[m]);
    if (sem[t] != 0.f) {
        size_t base = ((size_t)src*N + t)*K19;
        #pragma unroll
        for (int s = 0; s < K19; ++s) {
            int j = ci[base + s];
            float v = cv[base + s];
            if (sem[j] != 0.f) TOPK_INSERT(KM, vals, inds, v, j);
        }
    } else {
        #pragma unroll
        for (int s = 0; s < KM; ++s) {
            float v = gvv[s]; int j = gii[s];
            TOPK_INSERT(KM, vals, inds, v, j);
        }
    }
    int* o = idx_out + ((size_t)b*N + t)*KM;
    #pragma unroll
    for (int s = 0; s < KM; ++s) o[s] = inds[s];
}

// ---------------- weight prep ---------------------------------------------------
__global__ void k_prep_w(const float* __restrict__ w, const float* __restrict__ g,
                         const float* __restrict__ bb, const float* __restrict__ m,
                         const float* __restrict__ v,
                         float* __restrict__ wAt, float* __restrict__ wDt,
                         float* __restrict__ wS, float* __restrict__ bias) {
    int e = blockIdx.x*blockDim.x + threadIdx.x;
    if (e >= C*O) return;
    int o = e & 63, c = e >> 6;
    float s = g[o] / sqrtf(v[o] + EPSBN);
    float wa = w[o*128 + c]      * s;
    float wc = w[o*128 + 64 + c] * s;
    wAt[c*O + o] = wa;
    wDt[c*O + o] = wc - wa;
    wS [c*O + o] = wc;
    if (c == 0) bias[o] = bb[o] - m[o]*s;
}

// ---------------- stage1: mean + erasevec + biasvec0 ------------------------------
__global__ void k_stage1(const float* __restrict__ x,
                         const float* __restrict__ we, const float* __restrict__ be,
                         const float* __restrict__ ge, const float* __restrict__ bee,
                         const float* __restrict__ me, const float* __restrict__ ve,
                         const float* __restrict__ wS0, const float* __restrict__ bias0,
                         float* __restrict__ bv0) {
    __shared__ float sres[64], syv[64];
    int b = blockIdx.x, t = threadIdx.x;
    int w = t >> 5, l = t & 31;
    #pragma unroll
    for (int u = 0; u < 4; ++u) {
        int c = w*4 + u;
        const float* p = x + ((size_t)b*C + c)*N;
        float s = 0.f;
        #pragma unroll
        for (int n0 = 0; n0 < 16; ++n0) s += p[n0*32 + l];
        #pragma unroll
        for (int off = 16; off > 0; off >>= 1) s += __shfl_down_sync(~0u, s, off);
        if (l == 0) sres[c] = s * (1.f/N);
    }
    __syncthreads();
    if (t < 64) {
        float a = 0.f;
        #pragma unroll 8
        for (int cc = 0; cc < C; ++cc) a += we[t*C + cc]*sres[cc];
        a += be[t];
        float sc = ge[t] / sqrtf(ve[t] + EPSBN);
        syv[t] = (a - me[t])*sc + bee[t];
    }
    __syncthreads();
    if (t < 64) {
        float a = bias0[t];
        #pragma unroll 8
        for (int cc = 0; cc < C; ++cc) a += wS0[cc*O + t]*syv[cc];
        bv0[b*O + t] = a;
    }
}

// ---------------- A/D GEMMs --------------------------------------------------------
__global__ void k_gemm(const float* __restrict__ x, const float* __restrict__ wAt,
                       const float* __restrict__ wDt,
                       float* __restrict__ At, float* __restrict__ Dt, int remap) {
    __shared__ float xs [C*64];
    __shared__ float swA[C*O];
    __shared__ float swD[C*O];
    int b = blockIdx.y, jc = blockIdx.x;
    int bsrc = remap ? srcmap(b) : b;
    int t = threadIdx.x;
    for (int e = t; e < C*O; e += 256) { swA[e] = wAt[e]; swD[e] = wDt[e]; }
    const float* xb = x + (size_t)bsrc*C*N + jc*64;
    for (int e = t; e < C*64; e += 256) {
        int c = e >> 6, jj = e & 63;
        xs[c*64 + jj] = xb[c*N + jj];
    }
    __syncthreads();
    int og = t & 15, jt = t >> 4;
    float a[4][4] = {}, d[4][4] = {};
    #pragma unroll 4
    for (int c = 0; c < C; ++c) {
        float4 wa = *(const float4*)(swA + c*O + og*4);
        float4 wd = *(const float4*)(swD + c*O + og*4);
        float4 xv = *(const float4*)(xs  + c*64 + jt*4);
        float xw[4]  = {xv.x, xv.y, xv.z, xv.w};
        float wav[4] = {wa.x, wa.y, wa.z, wa.w};
        float wdv[4] = {wd.x, wd.y, wd.z, wd.w};
        #pragma unroll
        for (int oo = 0; oo < 4; ++oo)
            #pragma unroll
            for (int jj = 0; jj < 4; ++jj) {
                a[oo][jj] += wav[oo]*xw[jj];
                d[oo][jj] += wdv[oo]*xw[jj];
            }
    }
    int jbase = jc*64 + jt*4;
    #pragma unroll
    for (int jj = 0; jj < 4; ++jj) {
        float4 va = make_float4(a[0][jj], a[1][jj], a[2][jj], a[3][jj]);
        float4 vd = make_float4(d[0][jj], d[1][jj], d[2][jj], d[3][jj]);
        *(float4*)(At + ((size_t)b*N + jbase + jj)*O + og*4) = va;
        *(float4*)(Dt + ((size_t)b*N + jbase + jj)*O + og*4) = vd;
    }
}

// ---------------- edge pool + n-pool fused -------------------------------------------
// HAS_EM=false: branch 0, neighbor lists read from K19 cache (stride 19, first 10)
// HAS_EM=true : branch 1, lists from idx (stride 10)
#define EP_SMEM_BYTES (N*O*4 + N*KM*4 + N*4 + 16*64*4*2)
template<bool HAS_EM>
__global__ __launch_bounds__(512, 1)
void k_edgepool(const float* __restrict__ At, const float* __restrict__ Dt,
                const int* __restrict__ idx, const float* __restrict__ em,
                const float* __restrict__ bvec, float* __restrict__ out,
                float* __restrict__ xv, int add) {
    float* sA   = (float*)s_dyn;                          // [512][64]
    int*   sI   = (int*)(s_dyn + N*O*4);                  // [512][10]
    float* sEm  = (float*)(s_dyn + N*O*4 + N*KM*4);       // [512]
    float* rmax = sEm + N;                                // [16][64]
    float* rsum = rmax + 16*64;                           // [16][64]
    int b = blockIdx.x, t = threadIdx.x;
    {
        const float4* src = (const float4*)(At + (size_t)b*N*O);
        float4* dst = (float4*)sA;
        for (int e = t; e < N*O/4; e += 512) dst[e] = src[e];
        if (HAS_EM) {
            const int* isrc = idx + (size_t)b*N*KM;
            for (int e = t; e < N*KM; e += 512) sI[e] = isrc[e];
            sEm[t] = em[b*N + t];
        } else {
            const int* isrc = idx + (size_t)b*N*K19;   // K19 cache inds
            for (int e = t; e < N*KM; e += 512) {
                int q = e / KM, k = e % KM;
                sI[e] = isrc[q*K19 + k];
            }
        }
    }
    __syncthreads();
    int w = t >> 5, l = t & 31;
    float2 bv = *(const float2*)(bvec + b*O + 2*l);
    float2 tmax = make_float2(-INFINITY, -INFINITY);
    float2 tsum = make_float2(0.f, 0.f);
    for (int ii = 0; ii < 32; ++ii) {
        int i = w*32 + ii;
        float2 mx = make_float2(-INFINITY, -INFINITY);
        #pragma unroll
        for (int k = 0; k < KM; ++k) {
            int jk = sI[i*KM + k];
            float2 v = *(const float2*)(sA + jk*O + 2*l);
            if (HAS_EM) { float e = sEm[jk]; v.x *= e; v.y *= e; }
            mx.x = fmaxf(mx.x, v.x); mx.y = fmaxf(mx.y, v.y);
        }
        float ei = HAS_EM ? sEm[i] : 1.f;
        float2 dt = *(const float2*)(Dt + ((size_t)b*N + i)*O + 2*l);
        float vx = mx.x + ei*dt.x + bv.x;
        float vy = mx.y + ei*dt.y + bv.y;
        vx = vx > 0.f ? vx : 0.2f*vx;
        vy = vy > 0.f ? vy : 0.2f*vy;
        tmax.x = fmaxf(tmax.x, vx); tmax.y = fmaxf(tmax.y, vy);
        tsum.x += vx;               tsum.y += vy;
    }
    *(float2*)(rmax + w*64 + 2*l) = tmax;
    *(float2*)(rsum + w*64 + 2*l) = tsum;
    __syncthreads();
    if (t < 64) {
        float m = -INFINITY, s2 = 0.f;
        #pragma unroll
        for (int wi2 = 0; wi2 < 16; ++wi2) {
            m  = fmaxf(m, rmax[wi2*64 + t]);
            s2 += rsum[wi2*64 + t];
        }
        float mean = s2 * (1.f/N);
        if (add) { out[b*128 + t] += m; out[b*128 + 64 + t] += mean; }
        else     { out[b*128 + t]  = m; out[b*128 + 64 + t]  = mean;
                   if (xv) xv[b*O + t] = m; }
    }
}

// ---------------- stage2 (fused correlation + erase-vec) ---------------------------------
// idx8: first 8 of the K19 cache at src(b)
__global__ __launch_bounds__(512, 1)
void k_stage2(const float* __restrict__ xv, const float* __restrict__ wr,
              const float* __restrict__ x, const int* __restrict__ ci,
              const float* __restrict__ we, const float* __restrict__ be,
              const float* __restrict__ ge, const float* __restrict__ bee,
              const float* __restrict__ me, const float* __restrict__ ve,
              const float* __restrict__ wS1, const float* __restrict__ bias1,
              float* __restrict__ em_out, float* __restrict__ bv1) {
    __shared__ float sxv[64], sq[64], sres[64], syv[64];
    __shared__ float sf[512], sem[512], ssm[512], sred[512];
    __shared__ float sv[512];
    __shared__ int   si[512];
    int b = blockIdx.x, t = threadIdx.x;
    int src = srcmap(b);
    const float* x1b = x + (size_t)src*C*N;
    const int* ci_b = ci + (size_t)src*N*K19;

    if (t < 64) sxv[t] = xv[b*O + t];
    __syncthreads();
    if (t < 64) {
        float a = 0.f;
        #pragma unroll 8
        for (int c = 0; c < C; ++c) a += wr[t*C + c]*sxv[c];
        sq[t] = a;
    }
    __syncthreads();
    {
        float a = 0.f;
        const float* p = x1b + t;
        #pragma unroll 8
        for (int c = 0; c < C; ++c) a += sq[c]*p[c*N];
        sf[t] = a * 0.125f;
    }
    __syncthreads();
    {
        float fk = sf[t];
        const int* ip = ci_b + (size_t)t*K19;
        #pragma unroll
        for (int k = 0; k < KC; ++k) fk += sf[ip[k]];
        sv[t] = fk; si[t] = t;
    }
    __syncthreads();
    for (int s = 256; s > 0; s >>= 1) {
        if (t < s) {
            float v2 = sv[t+s]; int i2 = si[t+s];
            if (v2 > sv[t] || (v2 == sv[t] && i2 < si[t])) { sv[t] = v2; si[t] = i2; }
        }
        __syncthreads();
    }
    int index = si[0];
    sem[t] = 1.f;
    __syncthreads();
    if (t < KC) sem[ci_b[(size_t)index*K19 + t]] = 0.f;
    if (t == KC) sem[index] = 0.f;
    __syncthreads();
    float s_ = sf[t] - (1.f - sem[t])*1e8f;
    sred[t] = s_;
    __syncthreads();
    for (int st = 256; st > 0; st >>= 1) {
        if (t < st) sred[t] = fmaxf(sred[t], sred[t+st]);
        __syncthreads();
    }
    float mxv = sred[0];
    __syncthreads();
    float e = expf(s_ - mxv);
    sred[t] = e;
    __syncthreads();
    for (int st = 256; st > 0; st >>= 1) {
        if (t < st) sred[t] += sred[t+st];
        __syncthreads();
    }
    float ssum = sred[0];
    __syncthreads();
    ssm[t] = e / ssum;
    __syncthreads();
    {
        int w = t >> 5, l = t & 31;
        #pragma unroll
        for (int u = 0; u < 4; ++u) {
            int c = w*4 + u;
            const float* p = x1b + (size_t)c*N;
            float s = 0.f;
            #pragma unroll
            for (int n0 = 0; n0 < 16; ++n0) { int n = n0*32 + l; s += p[n]*ssm[n]; }
            #pragma unroll
            for (int off = 16; off > 0; off >>= 1) s += __shfl_down_sync(~0u, s, off);
            if (l == 0) sres[c] = s;
        }
    }
    __syncthreads();
    if (t < 64) {
        float a = 0.f;
        #pragma unroll 8
        for (int c = 0; c < C; ++c) a += we[t*C + c]*sres[c];
        a += be[t];
        float sc = ge[t] / sqrtf(ve[t] + EPSBN);
        syv[t] = (a - me[t])*sc + bee[t];
    }
    __syncthreads();
    if (t < 64) {
        float a = bias1[t];
        #pragma unroll 8
        for (int c = 0; c < C; ++c) a += wS1[c*O + t]*syv[c];
        bv1[b*O + t] = a;
    }
    em_out[b*N + t] = sem[t];
}

// =============================================================================
extern "C" void kernel_launch(void* const* d_in, const int* in_sizes, int n_in,
                              void* d_out, int out_size) {
    const float* x        = (const float*)d_in[0];
    const float* w_reduce = (const float*)d_in[1];
    const float* w_erase  = (const float*)d_in[2];
    const float* b_erase  = (const float*)d_in[3];
    const float* g_erase  = (const float*)d_in[4];
    const float* be_erase = (const float*)d_in[5];
    const float* m_erase  = (const float*)d_in[6];
    const float* v_erase  = (const float*)d_in[7];
    const float* w0 = (const float*)d_in[8];
    const float* g0 = (const float*)d_in[9];
    const float* b0 = (const float*)d_in[10];
    const float* m0 = (const float*)d_in[11];
    const float* v0 = (const float*)d_in[12];
    const float* w1 = (const float*)d_in[13];
    const float* g1 = (const float*)d_in[14];
    const float* b1 = (const float*)d_in[15];
    const float* m1 = (const float*)d_in[16];
    const float* v1 = (const float*)d_in[17];
    float* out = (float*)d_out;

    float *p_xt, *p_cv, *p_At0, *p_Dt0, *p_At1, *p_Dt1;
    float *p_em, *p_xv, *p_bv0, *p_bv1, *p_wAt, *p_wDt, *p_wS, *p_bias;
    int *p_ci, *p_idx;
    cudaGetSymbolAddress((void**)&p_xt,  g_xt);
    cudaGetSymbolAddress((void**)&p_cv,  g_cv);
    cudaGetSymbolAddress((void**)&p_ci,  g_ci);
    cudaGetSymbolAddress((void**)&p_At0, g_At0);
    cudaGetSymbolAddress((void**)&p_Dt0, g_Dt0);
    cudaGetSymbolAddress((void**)&p_At1, g_At1);
    cudaGetSymbolAddress((void**)&p_Dt1, g_Dt1);
    cudaGetSymbolAddress((void**)&p_em,  g_em);
    cudaGetSymbolAddress((void**)&p_xv,  g_xv);
    cudaGetSymbolAddress((void**)&p_bv0, g_bv0);
    cudaGetSymbolAddress((void**)&p_bv1, g_bv1);
    cudaGetSymbolAddress((void**)&p_wAt, g_wAt);
    cudaGetSymbolAddress((void**)&p_wDt, g_wDt);
    cudaGetSymbolAddress((void**)&p_wS,  g_wS);
    cudaGetSymbolAddress((void**)&p_bias,g_bias);
    cudaGetSymbolAddress((void**)&p_idx, g_idx);

    cudaFuncSetAttribute((const void*)knn19, cudaFuncAttributeMaxDynamicSharedMemorySize, KNN_SMEM_BYTES);
    cudaFuncSetAttribute((const void*)k_edgepool<false>, cudaFuncAttributeMaxDynamicSharedMemorySize, EP_SMEM_BYTES);
    cudaFuncSetAttribute((const void*)k_edgepool<true>,  cudaFuncAttributeMaxDynamicSharedMemorySize, EP_SMEM_BYTES);

    k_prep_w<<<16, 256>>>(w0, g0, b0, m0, v0, p_wAt,       p_wDt,       p_wS,       p_bias);
    k_prep_w<<<16, 256>>>(w1, g1, b1, m1, v1, p_wAt + C*O, p_wDt + C*O, p_wS + C*O, p_bias + O);

    k_split<<<dim3(8, BATCH), 256>>>(x, p_xt);

    // single K19 scan over the 96 unique point sets (serves both tasks)
    knn19<<<2*BATCH, 256, KNN_SMEM_BYTES>>>((const float4*)p_xt, p_cv, p_ci);

    k_stage1<<<BATCH, 512>>>(x, w_erase, b_erase, g_erase, be_erase, m_erase, v_erase,
                             p_wS, p_bias, p_bv0);

    k_gemm<<<dim3(8, BATCH), 256>>>(x, p_wAt,       p_wDt,       p_At0, p_Dt0, 0);
    k_gemm<<<dim3(8, BATCH), 256>>>(x, p_wAt + C*O, p_wDt + C*O, p_At1, p_Dt1, 1);

    // branch 0 (idx10 = first 10 of K19 cache, read in-place)
    k_edgepool<false><<<BATCH, 512, EP_SMEM_BYTES>>>(p_At0, p_Dt0, p_ci, nullptr, p_bv0,
                                                     out, p_xv, 0);

    // correlation / erase #2 (idx8 = first 8 of cache at src(b))
    k_stage2<<<BATCH, 512>>>(p_xv, w_reduce, x, p_ci,
                             w_erase, b_erase, g_erase, be_erase, m_erase, v_erase,
                             p_wS + C*O, p_bias + O, p_em, p_bv1);

    // branch-1 knn from cache at src(b) + mask
    k_patch<<<BATCH, 512>>>(p_xt, p_em, p_cv, p_ci, p_idx);

    // branch 1
    k_edgepool<true><<<BATCH, 512, EP_SMEM_BYTES>>>(p_At1, p_Dt1, p_idx, p_em, p_bv1,
                                                    out, nullptr, 1);
}

// round 14
// speedup vs baseline: 2.3649x; 1.0563x over previous
#include <cuda_runtime.h>
#include <math.h>
#include <stdint.h>

#define BATCH 96
#define C 64
#define N 512
#define O 64
#define KM 10
#define KC 8
#define K19 19
#define EPSBN 1e-5f

extern __shared__ char s_dyn[];

__device__ __forceinline__ int srcmap(int b) {
    int b0 = b/12, tt = b%12;
    int t2 = tt+1 > 11 ? 11 : tt+1;
    return b0*12 + t2;
}

// ---------------- scratch -----------------------------------------------------
__device__ float g_xt [(size_t)BATCH*N*68];   // [b][p][64ch|norm|pad3] fp32
__device__ float g_cvh[(size_t)2*BATCH*N*K19]; // half-scan vals [b*2+half][q][19]
__device__ int   g_cih[(size_t)2*BATCH*N*K19];
__device__ float g_cv [(size_t)BATCH*N*K19];  // merged per-b top-19 vals
__device__ int   g_ci [(size_t)BATCH*N*K19];
__device__ float g_At0[BATCH*N*O];
__device__ float g_Dt0[BATCH*N*O];
__device__ float g_At1[BATCH*N*O];
__device__ float g_Dt1[BATCH*N*O];
__device__ int   g_idx [BATCH*N*KM];          // branch-1 knn (patch output)
__device__ float g_em  [BATCH*N];
__device__ float g_xv  [BATCH*O];
__device__ float g_bv0 [BATCH*O];
__device__ float g_bv1 [BATCH*O];
__device__ float g_wAt [2][C*O];
__device__ float g_wDt [2][C*O];
__device__ float g_wS  [2][C*O];
__device__ float g_bias[2][O];

// ---------------- packed f32x2 ops ---------------------------------------------
__device__ __forceinline__ unsigned long long fma2(unsigned long long a,
                                                   unsigned long long b,
                                                   unsigned long long c) {
    unsigned long long d;
    asm("fma.rn.f32x2 %0, %1, %2, %3;" : "=l"(d) : "l"(a), "l"(b), "l"(c));
    return d;
}
__device__ __forceinline__ unsigned long long mul2(unsigned long long a,
                                                   unsigned long long b) {
    unsigned long long d;
    asm("mul.rn.f32x2 %0, %1, %2;" : "=l"(d) : "l"(a), "l"(b));
    return d;
}
__device__ __forceinline__ float2 unpk(unsigned long long a) {
    float2 r;
    asm("mov.b64 {%0,%1}, %2;" : "=f"(r.x), "=f"(r.y) : "l"(a));
    return r;
}

#define TOPK_INSERT(K, VV, II, dv, jv) do { \
    if ((dv) > VV[(K)-1]) { \
        VV[(K)-1] = (dv); II[(K)-1] = (jv); \
        _Pragma("unroll") \
        for (int s_ = (K)-1; s_ > 0; --s_) { \
            if (VV[s_] > VV[s_-1]) { \
                float tv_ = VV[s_]; VV[s_] = VV[s_-1]; VV[s_-1] = tv_; \
                int   ti_ = II[s_]; II[s_] = II[s_-1]; II[s_-1] = ti_; \
            } \
        } \
    } \
} while(0)

// ---------------- split/transpose prep: x -> [b][p][68] fp32 --------------------
__global__ void k_split(const float* __restrict__ x, float* __restrict__ xt) {
    __shared__ float tile[64*65];
    int jc = blockIdx.x, b = blockIdx.y;
    const float* src = x + (size_t)b*C*N + jc*64;
    int t = threadIdx.x;
    for (int e = t; e < 64*64; e += 256) {
        int c = e >> 6, jj = e & 63;
        tile[c*65 + jj] = src[c*N + jj];
    }
    __syncthreads();
    float* dst = xt + ((size_t)b*N + jc*64)*68;
    for (int u = t; u < 64*16; u += 256) {
        int p = u >> 4, ch = u & 15, c0 = ch*4;
        float4 v = make_float4(tile[(c0  )*65 + p], tile[(c0+1)*65 + p],
                               tile[(c0+2)*65 + p], tile[(c0+3)*65 + p]);
        *(float4*)(dst + p*68 + c0) = v;
    }
    if (t < 64) {
        float s = 0.f;
        #pragma unroll 8
        for (int c = 0; c < 64; ++c) { float v = tile[c*65 + t]; s += v*v; }
        *(float4*)(dst + t*68 + 64) = make_float4(s, 0.f, 0.f, 0.f);
    }
}

// ---------------- KNN: K19 half-range scan ----------------------------------------
#define KNN_SMEM_BYTES (N*68*4)

__global__ __launch_bounds__(256, 1)
void knn19h(const float4* __restrict__ xt, float* __restrict__ cvh, int* __restrict__ cih) {
    const int t = threadIdx.x;
    const int bid = blockIdx.x;        // [b][chunk][half]
    const int half  = bid & 1;
    const int chunk = (bid >> 1) & 1;
    const int b     = bid >> 2;

    const float4* src = xt + (size_t)b*N*17;
    float* sp = (float*)s_dyn;
    float4* spv = (float4*)s_dyn;
    for (int e = t; e < N*17; e += 256) spv[e] = src[e];
    __syncthreads();

    const int i = chunk*256 + t;
    ulonglong2 q[16];
    {
        unsigned long long two;
        asm("mov.b64 %0, {%1,%1};" : "=l"(two) : "f"(2.0f));
        const ulonglong2* qp = (const ulonglong2*)(sp + i*68);
        #pragma unroll
        for (int u = 0; u < 16; ++u) {
            ulonglong2 v = qp[u];
            q[u].x = mul2(v.x, two);
            q[u].y = mul2(v.y, two);
        }
    }

    float vals[K19]; int inds[K19];
    #pragma unroll
    for (int s = 0; s < K19; ++s) { vals[s] = -INFINITY; inds[s] = 0; }
    const int j0 = half*256;
    for (int j = j0; j < j0 + 256; ++j) {
        const ulonglong2* p = (const ulonglong2*)(sp + j*68);
        unsigned long long a0=0ull, a1=0ull, a2=0ull, a3=0ull;
        #pragma unroll
        for (int u = 0; u < 16; u += 4) {
            ulonglong2 v0 = p[u], v1 = p[u+1], v2 = p[u+2], v3 = p[u+3];
            a0 = fma2(q[u].x,   v0.x, a0);
            a1 = fma2(q[u].y,   v0.y, a1);
            a2 = fma2(q[u+1].x, v1.x, a2);
            a3 = fma2(q[u+1].y, v1.y, a3);
            a0 = fma2(q[u+2].x, v2.x, a0);
            a1 = fma2(q[u+2].y, v2.y, a1);
            a2 = fma2(q[u+3].x, v3.x, a2);
            a3 = fma2(q[u+3].y, v3.y, a3);
        }
        float n0 = sp[j*68 + 64];
        float2 f0 = unpk(a0), f1 = unpk(a1), f2 = unpk(a2), f3 = unpk(a3);
        float d = (((f0.x + f0.y) + (f1.x + f1.y))
                 + ((f2.x + f2.y) + (f3.x + f3.y))) - n0;
        TOPK_INSERT(K19, vals, inds, d, j);
    }
    size_t base = (((size_t)b*2 + half)*N + i)*K19;
    #pragma unroll
    for (int s = 0; s < K19; ++s) { cvh[base+s] = vals[s]; cih[base+s] = inds[s]; }
}

// ---------------- merge two half top-19 lists --------------------------------------
__global__ __launch_bounds__(512, 1)
void k_merge19(const float* __restrict__ cvh, const int* __restrict__ cih,
               float* __restrict__ cv, int* __restrict__ ci) {
    int b = blockIdx.x, q = threadIdx.x;
    float vals[K19]; int inds[K19];
    size_t baseA = (((size_t)b*2 + 0)*N + q)*K19;
    size_t baseB = (((size_t)b*2 + 1)*N + q)*K19;
    #pragma unroll
    for (int s = 0; s < K19; ++s) { vals[s] = cvh[baseA+s]; inds[s] = cih[baseA+s]; }
    #pragma unroll
    for (int s = 0; s < K19; ++s) {
        float v = cvh[baseB+s]; int id = cih[baseB+s];
        TOPK_INSERT(K19, vals, inds, v, id);
    }
    size_t base = ((size_t)b*N + q)*K19;
    #pragma unroll
    for (int s = 0; s < K19; ++s) { cv[base+s] = vals[s]; ci[base+s] = inds[s]; }
}

// ---------------- patch: branch-1 knn from cached top-19 + mask -------------------
__global__ __launch_bounds__(512, 1)
void k_patch(const float* __restrict__ xt, const float* __restrict__ em,
             const float* __restrict__ cv, const int* __restrict__ ci,
             int* __restrict__ idx_out) {
    __shared__ float sem[N];
    __shared__ float snm[N];
    __shared__ int   sM[16];
    __shared__ int   snM;
    __shared__ float wv[32*KM];
    __shared__ int   wi[32*KM];
    __shared__ float gvv[KM];
    __shared__ int   gii[KM];
    int b = blockIdx.x, t = threadIdx.x;
    int src = srcmap(b);
    sem[t] = em[b*N + t];
    snm[t] = xt[((size_t)src*N + t)*68 + 64];
    __syncthreads();
    if (t == 0) {
        int n = 0;
        for (int j = 0; j < N; ++j)
            if (sem[j] == 0.f && n < 16) sM[n++] = j;
        snM = n;
    }
    if (t < 32) {
        float v[KM]; int id[KM];
        #pragma unroll
        for (int s = 0; s < KM; ++s) { v[s] = -INFINITY; id[s] = 0; }
        for (int e = 0; e < 16; ++e) {
            int j = t*16 + e;
            if (sem[j] != 0.f) { float d = -snm[j]; TOPK_INSERT(KM, v, id, d, j); }
        }
        #pragma unroll
        for (int s = 0; s < KM; ++s) { wv[t*KM + s] = v[s]; wi[t*KM + s] = id[s]; }
    }
    __syncthreads();
    if (t == 0) {
        float v[KM]; int id[KM];
        #pragma unroll
        for (int s = 0; s < KM; ++s) { v[s] = -INFINITY; id[s] = 0; }
        for (int l = 0; l < 32; ++l)
            for (int s = 0; s < KM; ++s) {
                float vv = wv[l*KM + s]; int ii = wi[l*KM + s];
                TOPK_INSERT(KM, v, id, vv, ii);
            }
        #pragma unroll
        for (int s = 0; s < KM; ++s) { gvv[s] = v[s]; gii[s] = id[s]; }
    }
    __syncthreads();

    float vals[KM]; int inds[KM];
    #pragma unroll
    for (int s = 0; s < KM; ++s) { vals[s] = -INFINITY; inds[s] = 0; }
    int nM = snM;
    for (int m = 0; m < nM; ++m) TOPK_INSERT(KM, vals, inds, 0.f, sM[m]);
    if (sem[t] != 0.f) {
        size_t base = ((size_t)src*N + t)*K19;
        #pragma unroll
        for (int s = 0; s < K19; ++s) {
            int j = ci[base + s];
            float v = cv[base + s];
            if (sem[j] != 0.f) TOPK_INSERT(KM, vals, inds, v, j);
        }
    } else {
        #pragma unroll
        for (int s = 0; s < KM; ++s) {
            float v = gvv[s]; int j = gii[s];
            TOPK_INSERT(KM, vals, inds, v, j);
        }
    }
    int* o = idx_out + ((size_t)b*N + t)*KM;
    #pragma unroll
    for (int s = 0; s < KM; ++s) o[s] = inds[s];
}

// ---------------- weight prep ---------------------------------------------------
__global__ void k_prep_w(const float* __restrict__ w, const float* __restrict__ g,
                         const float* __restrict__ bb, const float* __restrict__ m,
                         const float* __restrict__ v,
                         float* __restrict__ wAt, float* __restrict__ wDt,
                         float* __restrict__ wS, float* __restrict__ bias) {
    int e = blockIdx.x*blockDim.x + threadIdx.x;
    if (e >= C*O) return;
    int o = e & 63, c = e >> 6;
    float s = g[o] / sqrtf(v[o] + EPSBN);
    float wa = w[o*128 + c]      * s;
    float wc = w[o*128 + 64 + c] * s;
    wAt[c*O + o] = wa;
    wDt[c*O + o] = wc - wa;
    wS [c*O + o] = wc;
    if (c == 0) bias[o] = bb[o] - m[o]*s;
}

// ---------------- stage1: mean + erasevec + biasvec0 ------------------------------
__global__ void k_stage1(const float* __restrict__ x,
                         const float* __restrict__ we, const float* __restrict__ be,
                         const float* __restrict__ ge, const float* __restrict__ bee,
                         const float* __restrict__ me, const float* __restrict__ ve,
                         const float* __restrict__ wS0, const float* __restrict__ bias0,
                         float* __restrict__ bv0) {
    __shared__ float sres[64], syv[64];
    int b = blockIdx.x, t = threadIdx.x;
    int w = t >> 5, l = t & 31;
    #pragma unroll
    for (int u = 0; u < 4; ++u) {
        int c = w*4 + u;
        const float* p = x + ((size_t)b*C + c)*N;
        float s = 0.f;
        #pragma unroll
        for (int n0 = 0; n0 < 16; ++n0) s += p[n0*32 + l];
        #pragma unroll
        for (int off = 16; off > 0; off >>= 1) s += __shfl_down_sync(~0u, s, off);
        if (l == 0) sres[c] = s * (1.f/N);
    }
    __syncthreads();
    if (t < 64) {
        float a = 0.f;
        #pragma unroll 8
        for (int cc = 0; cc < C; ++cc) a += we[t*C + cc]*sres[cc];
        a += be[t];
        float sc = ge[t] / sqrtf(ve[t] + EPSBN);
        syv[t] = (a - me[t])*sc + bee[t];
    }
    __syncthreads();
    if (t < 64) {
        float a = bias0[t];
        #pragma unroll 8
        for (int cc = 0; cc < C; ++cc) a += wS0[cc*O + t]*syv[cc];
        bv0[b*O + t] = a;
    }
}

// ---------------- A/D GEMMs --------------------------------------------------------
__global__ void k_gemm(const float* __restrict__ x, const float* __restrict__ wAt,
                       const float* __restrict__ wDt,
                       float* __restrict__ At, float* __restrict__ Dt, int remap) {
    __shared__ float xs [C*64];
    __shared__ float swA[C*O];
    __shared__ float swD[C*O];
    int b = blockIdx.y, jc = blockIdx.x;
    int bsrc = remap ? srcmap(b) : b;
    int t = threadIdx.x;
    for (int e = t; e < C*O; e += 256) { swA[e] = wAt[e]; swD[e] = wDt[e]; }
    const float* xb = x + (size_t)bsrc*C*N + jc*64;
    for (int e = t; e < C*64; e += 256) {
        int c = e >> 6, jj = e & 63;
        xs[c*64 + jj] = xb[c*N + jj];
    }
    __syncthreads();
    int og = t & 15, jt = t >> 4;
    float a[4][4] = {}, d[4][4] = {};
    #pragma unroll 4
    for (int c = 0; c < C; ++c) {
        float4 wa = *(const float4*)(swA + c*O + og*4);
        float4 wd = *(const float4*)(swD + c*O + og*4);
        float4 xv = *(const float4*)(xs  + c*64 + jt*4);
        float xw[4]  = {xv.x, xv.y, xv.z, xv.w};
        float wav[4] = {wa.x, wa.y, wa.z, wa.w};
        float wdv[4] = {wd.x, wd.y, wd.z, wd.w};
        #pragma unroll
        for (int oo = 0; oo < 4; ++oo)
            #pragma unroll
            for (int jj = 0; jj < 4; ++jj) {
                a[oo][jj] += wav[oo]*xw[jj];
                d[oo][jj] += wdv[oo]*xw[jj];
            }
    }
    int jbase = jc*64 + jt*4;
    #pragma unroll
    for (int jj = 0; jj < 4; ++jj) {
        float4 va = make_float4(a[0][jj], a[1][jj], a[2][jj], a[3][jj]);
        float4 vd = make_float4(d[0][jj], d[1][jj], d[2][jj], d[3][jj]);
        *(float4*)(At + ((size_t)b*N + jbase + jj)*O + og*4) = va;
        *(float4*)(Dt + ((size_t)b*N + jbase + jj)*O + og*4) = vd;
    }
}

// ---------------- edge pool + n-pool fused -------------------------------------------
#define EP_SMEM_BYTES (N*O*4 + N*KM*4 + N*4 + 16*64*4*2)
template<bool HAS_EM>
__global__ __launch_bounds__(512, 1)
void k_edgepool(const float* __restrict__ At, const float* __restrict__ Dt,
                const int* __restrict__ idx, const float* __restrict__ em,
                const float* __restrict__ bvec, float* __restrict__ out,
                float* __restrict__ xv, int add) {
    float* sA   = (float*)s_dyn;
    int*   sI   = (int*)(s_dyn + N*O*4);
    float* sEm  = (float*)(s_dyn + N*O*4 + N*KM*4);
    float* rmax = sEm + N;
    float* rsum = rmax + 16*64;
    int b = blockIdx.x, t = threadIdx.x;
    {
        const float4* src = (const float4*)(At + (size_t)b*N*O);
        float4* dst = (float4*)sA;
        for (int e = t; e < N*O/4; e += 512) dst[e] = src[e];
        if (HAS_EM) {
            const int* isrc = idx + (size_t)b*N*KM;
            for (int e = t; e < N*KM; e += 512) sI[e] = isrc[e];
            sEm[t] = em[b*N + t];
        } else {
            const int* isrc = idx + (size_t)b*N*K19;
            for (int e = t; e < N*KM; e += 512) {
                int q = e / KM, k = e % KM;
                sI[e] = isrc[q*K19 + k];
            }
        }
    }
    __syncthreads();
    int w = t >> 5, l = t & 31;
    float2 bv = *(const float2*)(bvec + b*O + 2*l);
    float2 tmax = make_float2(-INFINITY, -INFINITY);
    float2 tsum = make_float2(0.f, 0.f);
    for (int ii = 0; ii < 32; ++ii) {
        int i = w*32 + ii;
        float2 mx = make_float2(-INFINITY, -INFINITY);
        #pragma unroll
        for (int k = 0; k < KM; ++k) {
            int jk = sI[i*KM + k];
            float2 v = *(const float2*)(sA + jk*O + 2*l);
            if (HAS_EM) { float e = sEm[jk]; v.x *= e; v.y *= e; }
            mx.x = fmaxf(mx.x, v.x); mx.y = fmaxf(mx.y, v.y);
        }
        float ei = HAS_EM ? sEm[i] : 1.f;
        float2 dt = *(const float2*)(Dt + ((size_t)b*N + i)*O + 2*l);
        float vx = mx.x + ei*dt.x + bv.x;
        float vy = mx.y + ei*dt.y + bv.y;
        vx = vx > 0.f ? vx : 0.2f*vx;
        vy = vy > 0.f ? vy : 0.2f*vy;
        tmax.x = fmaxf(tmax.x, vx); tmax.y = fmaxf(tmax.y, vy);
        tsum.x += vx;               tsum.y += vy;
    }
    *(float2*)(rmax + w*64 + 2*l) = tmax;
    *(float2*)(rsum + w*64 + 2*l) = tsum;
    __syncthreads();
    if (t < 64) {
        float m = -INFINITY, s2 = 0.f;
        #pragma unroll
        for (int wi2 = 0; wi2 < 16; ++wi2) {
            m  = fmaxf(m, rmax[wi2*64 + t]);
            s2 += rsum[wi2*64 + t];
        }
        float mean = s2 * (1.f/N);
        if (add) { out[b*128 + t] += m; out[b*128 + 64 + t] += mean; }
        else     { out[b*128 + t]  = m; out[b*128 + 64 + t]  = mean;
                   if (xv) xv[b*O + t] = m; }
    }
}

// ---------------- stage2 (fused correlation + erase-vec) ---------------------------------
__global__ __launch_bounds__(512, 1)
void k_stage2(const float* __restrict__ xv, const float* __restrict__ wr,
              const float* __restrict__ x, const int* __restrict__ ci,
              const float* __restrict__ we, const float* __restrict__ be,
              const float* __restrict__ ge, const float* __restrict__ bee,
              const float* __restrict__ me, const float* __restrict__ ve,
              const float* __restrict__ wS1, const float* __restrict__ bias1,
              float* __restrict__ em_out, float* __restrict__ bv1) {
    __shared__ float sxv[64], sq[64], sres[64], syv[64];
    __shared__ float sf[512], sem[512], ssm[512], sred[512];
    __shared__ float sv[512];
    __shared__ int   si[512];
    int b = blockIdx.x, t = threadIdx.x;
    int src = srcmap(b);
    const float* x1b = x + (size_t)src*C*N;
    const int* ci_b = ci + (size_t)src*N*K19;

    if (t < 64) sxv[t] = xv[b*O + t];
    __syncthreads();
    if (t < 64) {
        float a = 0.f;
        #pragma unroll 8
        for (int c = 0; c < C; ++c) a += wr[t*C + c]*sxv[c];
        sq[t] = a;
    }
    __syncthreads();
    {
        float a = 0.f;
        const float* p = x1b + t;
        #pragma unroll 8
        for (int c = 0; c < C; ++c) a += sq[c]*p[c*N];
        sf[t] = a * 0.125f;
    }
    __syncthreads();
    {
        float fk = sf[t];
        const int* ip = ci_b + (size_t)t*K19;
        #pragma unroll
        for (int k = 0; k < KC; ++k) fk += sf[ip[k]];
        sv[t] = fk; si[t] = t;
    }
    __syncthreads();
    for (int s = 256; s > 0; s >>= 1) {
        if (t < s) {
            float v2 = sv[t+s]; int i2 = si[t+s];
            if (v2 > sv[t] || (v2 == sv[t] && i2 < si[t])) { sv[t] = v2; si[t] = i2; }
        }
        __syncthreads();
    }
    int index = si[0];
    sem[t] = 1.f;
    __syncthreads();
    if (t < KC) sem[ci_b[(size_t)index*K19 + t]] = 0.f;
    if (t == KC) sem[index] = 0.f;
    __syncthreads();
    float s_ = sf[t] - (1.f - sem[t])*1e8f;
    sred[t] = s_;
    __syncthreads();
    for (int st = 256; st > 0; st >>= 1) {
        if (t < st) sred[t] = fmaxf(sred[t], sred[t+st]);
        __syncthreads();
    }
    float mxv = sred[0];
    __syncthreads();
    float e = expf(s_ - mxv);
    sred[t] = e;
    __syncthreads();
    for (int st = 256; st > 0; st >>= 1) {
        if (t < st) sred[t] += sred[t+st];
        __syncthreads();
    }
    float ssum = sred[0];
    __syncthreads();
    ssm[t] = e / ssum;
    __syncthreads();
    {
        int w = t >> 5, l = t & 31;
        #pragma unroll
        for (int u = 0; u < 4; ++u) {
            int c = w*4 + u;
            const float* p = x1b + (size_t)c*N;
            float s = 0.f;
            #pragma unroll
            for (int n0 = 0; n0 < 16; ++n0) { int n = n0*32 + l; s += p[n]*ssm[n]; }
            #pragma unroll
            for (int off = 16; off > 0; off >>= 1) s += __shfl_down_sync(~0u, s, off);
            if (l == 0) sres[c] = s;
        }
    }
    __syncthreads();
    if (t < 64) {
        float a = 0.f;
        #pragma unroll 8
        for (int c = 0; c < C; ++c) a += we[t*C + c]*sres[c];
        a += be[t];
        float sc = ge[t] / sqrtf(ve[t] + EPSBN);
        syv[t] = (a - me[t])*sc + bee[t];
    }
    __syncthreads();
    if (t < 64) {
        float a = bias1[t];
        #pragma unroll 8
        for (int c = 0; c < C; ++c) a += wS1[c*O + t]*syv[c];
        bv1[b*O + t] = a;
    }
    em_out[b*N + t] = sem[t];
}

// =============================================================================
extern "C" void kernel_launch(void* const* d_in, const int* in_sizes, int n_in,
                              void* d_out, int out_size) {
    const float* x        = (const float*)d_in[0];
    const float* w_reduce = (const float*)d_in[1];
    const float* w_erase  = (const float*)d_in[2];
    const float* b_erase  = (const float*)d_in[3];
    const float* g_erase  = (const float*)d_in[4];
    const float* be_erase = (const float*)d_in[5];
    const float* m_erase  = (const float*)d_in[6];
    const float* v_erase  = (const float*)d_in[7];
    const float* w0 = (const float*)d_in[8];
    const float* g0 = (const float*)d_in[9];
    const float* b0 = (const float*)d_in[10];
    const float* m0 = (const float*)d_in[11];
    const float* v0 = (const float*)d_in[12];
    const float* w1 = (const float*)d_in[13];
    const float* g1 = (const float*)d_in[14];
    const float* b1 = (const float*)d_in[15];
    const float* m1 = (const float*)d_in[16];
    const float* v1 = (const float*)d_in[17];
    float* out = (float*)d_out;

    float *p_xt, *p_cvh, *p_cv, *p_At0, *p_Dt0, *p_At1, *p_Dt1;
    float *p_em, *p_xv, *p_bv0, *p_bv1, *p_wAt, *p_wDt, *p_wS, *p_bias;
    int *p_cih, *p_ci, *p_idx;
    cudaGetSymbolAddress((void**)&p_xt,  g_xt);
    cudaGetSymbolAddress((void**)&p_cvh, g_cvh);
    cudaGetSymbolAddress((void**)&p_cih, g_cih);
    cudaGetSymbolAddress((void**)&p_cv,  g_cv);
    cudaGetSymbolAddress((void**)&p_ci,  g_ci);
    cudaGetSymbolAddress((void**)&p_At0, g_At0);
    cudaGetSymbolAddress((void**)&p_Dt0, g_Dt0);
    cudaGetSymbolAddress((void**)&p_At1, g_At1);
    cudaGetSymbolAddress((void**)&p_Dt1, g_Dt1);
    cudaGetSymbolAddress((void**)&p_em,  g_em);
    cudaGetSymbolAddress((void**)&p_xv,  g_xv);
    cudaGetSymbolAddress((void**)&p_bv0, g_bv0);
    cudaGetSymbolAddress((void**)&p_bv1, g_bv1);
    cudaGetSymbolAddress((void**)&p_wAt, g_wAt);
    cudaGetSymbolAddress((void**)&p_wDt, g_wDt);
    cudaGetSymbolAddress((void**)&p_wS,  g_wS);
    cudaGetSymbolAddress((void**)&p_bias,g_bias);
    cudaGetSymbolAddress((void**)&p_idx, g_idx);

    cudaFuncSetAttribute((const void*)knn19h, cudaFuncAttributeMaxDynamicSharedMemorySize, KNN_SMEM_BYTES);
    cudaFuncSetAttribute((const void*)k_edgepool<false>, cudaFuncAttributeMaxDynamicSharedMemorySize, EP_SMEM_BYTES);
    cudaFuncSetAttribute((const void*)k_edgepool<true>,  cudaFuncAttributeMaxDynamicSharedMemorySize, EP_SMEM_BYTES);

    k_prep_w<<<16, 256>>>(w0, g0, b0, m0, v0, p_wAt,       p_wDt,       p_wS,       p_bias);
    k_prep_w<<<16, 256>>>(w1, g1, b1, m1, v1, p_wAt + C*O, p_wDt + C*O, p_wS + C*O, p_bias + O);

    k_split<<<dim3(8, BATCH), 256>>>(x, p_xt);

    // K19 half-range scans over the 96 unique point sets, then exact merge
    knn19h<<<4*BATCH, 256, KNN_SMEM_BYTES>>>((const float4*)p_xt, p_cvh, p_cih);
    k_merge19<<<BATCH, 512>>>(p_cvh, p_cih, p_cv, p_ci);

    k_stage1<<<BATCH, 512>>>(x, w_erase, b_erase, g_erase, be_erase, m_erase, v_erase,
                             p_wS, p_bias, p_bv0);

    k_gemm<<<dim3(8, BATCH), 256>>>(x, p_wAt,       p_wDt,       p_At0, p_Dt0, 0);
    k_gemm<<<dim3(8, BATCH), 256>>>(x, p_wAt + C*O, p_wDt + C*O, p_At1, p_Dt1, 1);

    // branch 0 (idx10 = first 10 of K19 cache, read in-place)
    k_edgepool<false><<<BATCH, 512, EP_SMEM_BYTES>>>(p_At0, p_Dt0, p_ci, nullptr, p_bv0,
                                                     out, p_xv, 0);

    // correlation / erase #2 (idx8 = first 8 of cache at src(b))
    k_stage2<<<BATCH, 512>>>(p_xv, w_reduce, x, p_ci,
                             w_erase, b_erase, g_erase, be_erase, m_erase, v_erase,
                             p_wS + C*O, p_bias + O, p_em, p_bv1);

    // branch-1 knn from cache at src(b) + mask
    k_patch<<<BATCH, 512>>>(p_xt, p_em, p_cv, p_ci, p_idx);

    // branch 1
    k_edgepool<true><<<BATCH, 512, EP_SMEM_BYTES>>>(p_At1, p_Dt1, p_idx, p_em, p_bv1,
                                                    out, nullptr, 1);
}

// round 15
// speedup vs baseline: 2.5646x; 1.0844x over previous
#include <cuda_runtime.h>
#include <math.h>
#include <stdint.h>

#define BATCH 96
#define C 64
#define N 512
#define O 64
#define KM 10
#define KC 8
#define K19 19
#define EPSBN 1e-5f

extern __shared__ char s_dyn[];

__device__ __forceinline__ int srcmap(int b) {
    int b0 = b/12, tt = b%12;
    int t2 = tt+1 > 11 ? 11 : tt+1;
    return b0*12 + t2;
}

// ---------------- scratch -----------------------------------------------------
__device__ float g_xt [(size_t)BATCH*N*68];   // [b][p][64ch|norm|pad3] fp32
__device__ float g_cvh[(size_t)2*BATCH*N*K19]; // half-scan vals [b*2+half][q][19]
__device__ int   g_cih[(size_t)2*BATCH*N*K19];
__device__ float g_cv [(size_t)BATCH*N*K19];  // merged per-b top-19 vals
__device__ int   g_ci [(size_t)BATCH*N*K19];
__device__ float g_At0[BATCH*N*O];
__device__ float g_Dt0[BATCH*N*O];
__device__ float g_At1[BATCH*N*O];
__device__ float g_Dt1[BATCH*N*O];
__device__ int   g_idx [BATCH*N*KM];          // branch-1 knn (patch output)
__device__ float g_em  [BATCH*N];
__device__ float g_xv  [BATCH*O];
__device__ float g_bv0 [BATCH*O];
__device__ float g_bv1 [BATCH*O];
__device__ float g_wAt [2][C*O];
__device__ float g_wDt [2][C*O];
__device__ float g_wS  [2][C*O];
__device__ float g_bias[2][O];

// ---------------- packed f32x2 ops ---------------------------------------------
__device__ __forceinline__ unsigned long long fma2(unsigned long long a,
                                                   unsigned long long b,
                                                   unsigned long long c) {
    unsigned long long d;
    asm("fma.rn.f32x2 %0, %1, %2, %3;" : "=l"(d) : "l"(a), "l"(b), "l"(c));
    return d;
}
__device__ __forceinline__ unsigned long long mul2(unsigned long long a,
                                                   unsigned long long b) {
    unsigned long long d;
    asm("mul.rn.f32x2 %0, %1, %2;" : "=l"(d) : "l"(a), "l"(b));
    return d;
}
__device__ __forceinline__ float2 unpk(unsigned long long a) {
    float2 r;
    asm("mov.b64 {%0,%1}, %2;" : "=f"(r.x), "=f"(r.y) : "l"(a));
    return r;
}

#define TOPK_INSERT(K, VV, II, dv, jv) do { \
    if ((dv) > VV[(K)-1]) { \
        VV[(K)-1] = (dv); II[(K)-1] = (jv); \
        _Pragma("unroll") \
        for (int s_ = (K)-1; s_ > 0; --s_) { \
            if (VV[s_] > VV[s_-1]) { \
                float tv_ = VV[s_]; VV[s_] = VV[s_-1]; VV[s_-1] = tv_; \
                int   ti_ = II[s_]; II[s_] = II[s_-1]; II[s_-1] = ti_; \
            } \
        } \
    } \
} while(0)

// ---------------- split/transpose prep: x -> [b][p][68] fp32 --------------------
__global__ void k_split(const float* __restrict__ x, float* __restrict__ xt) {
    __shared__ float tile[64*65];
    int jc = blockIdx.x, b = blockIdx.y;
    const float* src = x + (size_t)b*C*N + jc*64;
    int t = threadIdx.x;
    for (int e = t; e < 64*64; e += 256) {
        int c = e >> 6, jj = e & 63;
        tile[c*65 + jj] = src[c*N + jj];
    }
    __syncthreads();
    float* dst = xt + ((size_t)b*N + jc*64)*68;
    for (int u = t; u < 64*16; u += 256) {
        int p = u >> 4, ch = u & 15, c0 = ch*4;
        float4 v = make_float4(tile[(c0  )*65 + p], tile[(c0+1)*65 + p],
                               tile[(c0+2)*65 + p], tile[(c0+3)*65 + p]);
        *(float4*)(dst + p*68 + c0) = v;
    }
    if (t < 64) {
        float s = 0.f;
        #pragma unroll 8
        for (int c = 0; c < 64; ++c) { float v = tile[c*65 + t]; s += v*v; }
        *(float4*)(dst + t*68 + 64) = make_float4(s, 0.f, 0.f, 0.f);
    }
}

// ---------------- KNN: K19 half-range scan, half table in smem --------------------
// 128 threads, 3 blocks/SM (69.6KB smem, 170 regs)
#define KNN_SMEM_BYTES (256*68*4)

__global__ __launch_bounds__(128, 3)
void knn19h(const float* __restrict__ xt, float* __restrict__ cvh, int* __restrict__ cih) {
    const int t = threadIdx.x;
    const int bid = blockIdx.x;        // [b][chunk(4)][half(2)]
    const int half  = bid & 1;
    const int chunk = (bid >> 1) & 3;
    const int b     = bid >> 3;

    // fill smem with THIS HALF's 256 point rows only
    float* sp = (float*)s_dyn;
    {
        const float4* src = (const float4*)(xt + ((size_t)b*N + half*256)*68);
        float4* spv = (float4*)sp;
        for (int e = t; e < 256*17; e += 128) spv[e] = src[e];
    }

    // query straight from global (272B row stride, 16B aligned)
    const int i = chunk*128 + t;
    ulonglong2 q[16];
    {
        unsigned long long two;
        asm("mov.b64 %0, {%1,%1};" : "=l"(two) : "f"(2.0f));
        const ulonglong2* qp = (const ulonglong2*)(xt + ((size_t)b*N + i)*68);
        #pragma unroll
        for (int u = 0; u < 16; ++u) {
            ulonglong2 v = qp[u];
            q[u].x = mul2(v.x, two);
            q[u].y = mul2(v.y, two);
        }
    }
    __syncthreads();

    float vals[K19]; int inds[K19];
    #pragma unroll
    for (int s = 0; s < K19; ++s) { vals[s] = -INFINITY; inds[s] = 0; }
    const int jg0 = half*256;
    for (int j = 0; j < 256; ++j) {
        const ulonglong2* p = (const ulonglong2*)(sp + j*68);
        unsigned long long a0=0ull, a1=0ull, a2=0ull, a3=0ull;
        #pragma unroll
        for (int u = 0; u < 16; u += 4) {
            ulonglong2 v0 = p[u], v1 = p[u+1], v2 = p[u+2], v3 = p[u+3];
            a0 = fma2(q[u].x,   v0.x, a0);
            a1 = fma2(q[u].y,   v0.y, a1);
            a2 = fma2(q[u+1].x, v1.x, a2);
            a3 = fma2(q[u+1].y, v1.y, a3);
            a0 = fma2(q[u+2].x, v2.x, a0);
            a1 = fma2(q[u+2].y, v2.y, a1);
            a2 = fma2(q[u+3].x, v3.x, a2);
            a3 = fma2(q[u+3].y, v3.y, a3);
        }
        float n0 = sp[j*68 + 64];
        float2 f0 = unpk(a0), f1 = unpk(a1), f2 = unpk(a2), f3 = unpk(a3);
        float d = (((f0.x + f0.y) + (f1.x + f1.y))
                 + ((f2.x + f2.y) + (f3.x + f3.y))) - n0;
        TOPK_INSERT(K19, vals, inds, d, jg0 + j);
    }
    size_t base = (((size_t)b*2 + half)*N + i)*K19;
    #pragma unroll
    for (int s = 0; s < K19; ++s) { cvh[base+s] = vals[s]; cih[base+s] = inds[s]; }
}

// ---------------- merge two half top-19 lists --------------------------------------
__global__ __launch_bounds__(512, 1)
void k_merge19(const float* __restrict__ cvh, const int* __restrict__ cih,
               float* __restrict__ cv, int* __restrict__ ci) {
    int b = blockIdx.x, q = threadIdx.x;
    float vals[K19]; int inds[K19];
    size_t baseA = (((size_t)b*2 + 0)*N + q)*K19;
    size_t baseB = (((size_t)b*2 + 1)*N + q)*K19;
    #pragma unroll
    for (int s = 0; s < K19; ++s) { vals[s] = cvh[baseA+s]; inds[s] = cih[baseA+s]; }
    #pragma unroll
    for (int s = 0; s < K19; ++s) {
        float v = cvh[baseB+s]; int id = cih[baseB+s];
        TOPK_INSERT(K19, vals, inds, v, id);
    }
    size_t base = ((size_t)b*N + q)*K19;
    #pragma unroll
    for (int s = 0; s < K19; ++s) { cv[base+s] = vals[s]; ci[base+s] = inds[s]; }
}

// ---------------- patch: branch-1 knn from cached top-19 + mask -------------------
__global__ __launch_bounds__(512, 1)
void k_patch(const float* __restrict__ xt, const float* __restrict__ em,
             const float* __restrict__ cv, const int* __restrict__ ci,
             int* __restrict__ idx_out) {
    __shared__ float sem[N];
    __shared__ float snm[N];
    __shared__ int   sM[16];
    __shared__ int   snM;
    __shared__ float wv[32*KM];
    __shared__ int   wi[32*KM];
    __shared__ float gvv[KM];
    __shared__ int   gii[KM];
    int b = blockIdx.x, t = threadIdx.x;
    int src = srcmap(b);
    sem[t] = em[b*N + t];
    snm[t] = xt[((size_t)src*N + t)*68 + 64];
    __syncthreads();
    if (t == 0) {
        int n = 0;
        for (int j = 0; j < N; ++j)
            if (sem[j] == 0.f && n < 16) sM[n++] = j;
        snM = n;
    }
    if (t < 32) {
        float v[KM]; int id[KM];
        #pragma unroll
        for (int s = 0; s < KM; ++s) { v[s] = -INFINITY; id[s] = 0; }
        for (int e = 0; e < 16; ++e) {
            int j = t*16 + e;
            if (sem[j] != 0.f) { float d = -snm[j]; TOPK_INSERT(KM, v, id, d, j); }
        }
        #pragma unroll
        for (int s = 0; s < KM; ++s) { wv[t*KM + s] = v[s]; wi[t*KM + s] = id[s]; }
    }
    __syncthreads();
    if (t == 0) {
        float v[KM]; int id[KM];
        #pragma unroll
        for (int s = 0; s < KM; ++s) { v[s] = -INFINITY; id[s] = 0; }
        for (int l = 0; l < 32; ++l)
            for (int s = 0; s < KM; ++s) {
                float vv = wv[l*KM + s]; int ii = wi[l*KM + s];
                TOPK_INSERT(KM, v, id, vv, ii);
            }
        #pragma unroll
        for (int s = 0; s < KM; ++s) { gvv[s] = v[s]; gii[s] = id[s]; }
    }
    __syncthreads();

    float vals[KM]; int inds[KM];
    #pragma unroll
    for (int s = 0; s < KM; ++s) { vals[s] = -INFINITY; inds[s] = 0; }
    int nM = snM;
    for (int m = 0; m < nM; ++m) TOPK_INSERT(KM, vals, inds, 0.f, sM[m]);
    if (sem[t] != 0.f) {
        size_t base = ((size_t)src*N + t)*K19;
        #pragma unroll
        for (int s = 0; s < K19; ++s) {
            int j = ci[base + s];
            float v = cv[base + s];
            if (sem[j] != 0.f) TOPK_INSERT(KM, vals, inds, v, j);
        }
    } else {
        #pragma unroll
        for (int s = 0; s < KM; ++s) {
            float v = gvv[s]; int j = gii[s];
            TOPK_INSERT(KM, vals, inds, v, j);
        }
    }
    int* o = idx_out + ((size_t)b*N + t)*KM;
    #pragma unroll
    for (int s = 0; s < KM; ++s) o[s] = inds[s];
}

// ---------------- weight prep ---------------------------------------------------
__global__ void k_prep_w(const float* __restrict__ w, const float* __restrict__ g,
                         const float* __restrict__ bb, const float* __restrict__ m,
                         const float* __restrict__ v,
                         float* __restrict__ wAt, float* __restrict__ wDt,
                         float* __restrict__ wS, float* __restrict__ bias) {
    int e = blockIdx.x*blockDim.x + threadIdx.x;
    if (e >= C*O) return;
    int o = e & 63, c = e >> 6;
    float s = g[o] / sqrtf(v[o] + EPSBN);
    float wa = w[o*128 + c]      * s;
    float wc = w[o*128 + 64 + c] * s;
    wAt[c*O + o] = wa;
    wDt[c*O + o] = wc - wa;
    wS [c*O + o] = wc;
    if (c == 0) bias[o] = bb[o] - m[o]*s;
}

// ---------------- stage1: mean + erasevec + biasvec0 ------------------------------
__global__ void k_stage1(const float* __restrict__ x,
                         const float* __restrict__ we, const float* __restrict__ be,
                         const float* __restrict__ ge, const float* __restrict__ bee,
                         const float* __restrict__ me, const float* __restrict__ ve,
                         const float* __restrict__ wS0, const float* __restrict__ bias0,
                         float* __restrict__ bv0) {
    __shared__ float sres[64], syv[64];
    int b = blockIdx.x, t = threadIdx.x;
    int w = t >> 5, l = t & 31;
    #pragma unroll
    for (int u = 0; u < 4; ++u) {
        int c = w*4 + u;
        const float* p = x + ((size_t)b*C + c)*N;
        float s = 0.f;
        #pragma unroll
        for (int n0 = 0; n0 < 16; ++n0) s += p[n0*32 + l];
        #pragma unroll
        for (int off = 16; off > 0; off >>= 1) s += __shfl_down_sync(~0u, s, off);
        if (l == 0) sres[c] = s * (1.f/N);
    }
    __syncthreads();
    if (t < 64) {
        float a = 0.f;
        #pragma unroll 8
        for (int cc = 0; cc < C; ++cc) a += we[t*C + cc]*sres[cc];
        a += be[t];
        float sc = ge[t] / sqrtf(ve[t] + EPSBN);
        syv[t] = (a - me[t])*sc + bee[t];
    }
    __syncthreads();
    if (t < 64) {
        float a = bias0[t];
        #pragma unroll 8
        for (int cc = 0; cc < C; ++cc) a += wS0[cc*O + t]*syv[cc];
        bv0[b*O + t] = a;
    }
}

// ---------------- A/D GEMMs --------------------------------------------------------
__global__ void k_gemm(const float* __restrict__ x, const float* __restrict__ wAt,
                       const float* __restrict__ wDt,
                       float* __restrict__ At, float* __restrict__ Dt, int remap) {
    __shared__ float xs [C*64];
    __shared__ float swA[C*O];
    __shared__ float swD[C*O];
    int b = blockIdx.y, jc = blockIdx.x;
    int bsrc = remap ? srcmap(b) : b;
    int t = threadIdx.x;
    for (int e = t; e < C*O; e += 256) { swA[e] = wAt[e]; swD[e] = wDt[e]; }
    const float* xb = x + (size_t)bsrc*C*N + jc*64;
    for (int e = t; e < C*64; e += 256) {
        int c = e >> 6, jj = e & 63;
        xs[c*64 + jj] = xb[c*N + jj];
    }
    __syncthreads();
    int og = t & 15, jt = t >> 4;
    float a[4][4] = {}, d[4][4] = {};
    #pragma unroll 4
    for (int c = 0; c < C; ++c) {
        float4 wa = *(const float4*)(swA + c*O + og*4);
        float4 wd = *(const float4*)(swD + c*O + og*4);
        float4 xv = *(const float4*)(xs  + c*64 + jt*4);
        float xw[4]  = {xv.x, xv.y, xv.z, xv.w};
        float wav[4] = {wa.x, wa.y, wa.z, wa.w};
        float wdv[4] = {wd.x, wd.y, wd.z, wd.w};
        #pragma unroll
        for (int oo = 0; oo < 4; ++oo)
            #pragma unroll
            for (int jj = 0; jj < 4; ++jj) {
                a[oo][jj] += wav[oo]*xw[jj];
                d[oo][jj] += wdv[oo]*xw[jj];
            }
    }
    int jbase = jc*64 + jt*4;
    #pragma unroll
    for (int jj = 0; jj < 4; ++jj) {
        float4 va = make_float4(a[0][jj], a[1][jj], a[2][jj], a[3][jj]);
        float4 vd = make_float4(d[0][jj], d[1][jj], d[2][jj], d[3][jj]);
        *(float4*)(At + ((size_t)b*N + jbase + jj)*O + og*4) = va;
        *(float4*)(Dt + ((size_t)b*N + jbase + jj)*O + og*4) = vd;
    }
}

// ---------------- edge pool + n-pool fused -------------------------------------------
#define EP_SMEM_BYTES (N*O*4 + N*KM*4 + N*4 + 16*64*4*2)
template<bool HAS_EM>
__global__ __launch_bounds__(512, 1)
void k_edgepool(const float* __restrict__ At, const float* __restrict__ Dt,
                const int* __restrict__ idx, const float* __restrict__ em,
                const float* __restrict__ bvec, float* __restrict__ out,
                float* __restrict__ xv, int add) {
    float* sA   = (float*)s_dyn;
    int*   sI   = (int*)(s_dyn + N*O*4);
    float* sEm  = (float*)(s_dyn + N*O*4 + N*KM*4);
    float* rmax = sEm + N;
    float* rsum = rmax + 16*64;
    int b = blockIdx.x, t = threadIdx.x;
    {
        const float4* src = (const float4*)(At + (size_t)b*N*O);
        float4* dst = (float4*)sA;
        for (int e = t; e < N*O/4; e += 512) dst[e] = src[e];
        if (HAS_EM) {
            const int* isrc = idx + (size_t)b*N*KM;
            for (int e = t; e < N*KM; e += 512) sI[e] = isrc[e];
            sEm[t] = em[b*N + t];
        } else {
            const int* isrc = idx + (size_t)b*N*K19;
            for (int e = t; e < N*KM; e += 512) {
                int q = e / KM, k = e % KM;
                sI[e] = isrc[q*K19 + k];
            }
        }
    }
    __syncthreads();
    int w = t >> 5, l = t & 31;
    float2 bv = *(const float2*)(bvec + b*O + 2*l);
    float2 tmax = make_float2(-INFINITY, -INFINITY);
    float2 tsum = make_float2(0.f, 0.f);
    for (int ii = 0; ii < 32; ++ii) {
        int i = w*32 + ii;
        float2 mx = make_float2(-INFINITY, -INFINITY);
        #pragma unroll
        for (int k = 0; k < KM; ++k) {
            int jk = sI[i*KM + k];
            float2 v = *(const float2*)(sA + jk*O + 2*l);
            if (HAS_EM) { float e = sEm[jk]; v.x *= e; v.y *= e; }
            mx.x = fmaxf(mx.x, v.x); mx.y = fmaxf(mx.y, v.y);
        }
        float ei = HAS_EM ? sEm[i] : 1.f;
        float2 dt = *(const float2*)(Dt + ((size_t)b*N + i)*O + 2*l);
        float vx = mx.x + ei*dt.x + bv.x;
        float vy = mx.y + ei*dt.y + bv.y;
        vx = vx > 0.f ? vx : 0.2f*vx;
        vy = vy > 0.f ? vy : 0.2f*vy;
        tmax.x = fmaxf(tmax.x, vx); tmax.y = fmaxf(tmax.y, vy);
        tsum.x += vx;               tsum.y += vy;
    }
    *(float2*)(rmax + w*64 + 2*l) = tmax;
    *(float2*)(rsum + w*64 + 2*l) = tsum;
    __syncthreads();
    if (t < 64) {
        float m = -INFINITY, s2 = 0.f;
        #pragma unroll
        for (int wi2 = 0; wi2 < 16; ++wi2) {
            m  = fmaxf(m, rmax[wi2*64 + t]);
            s2 += rsum[wi2*64 + t];
        }
        float mean = s2 * (1.f/N);
        if (add) { out[b*128 + t] += m; out[b*128 + 64 + t] += mean; }
        else     { out[b*128 + t]  = m; out[b*128 + 64 + t]  = mean;
                   if (xv) xv[b*O + t] = m; }
    }
}

// ---------------- stage2 (fused correlation + erase-vec) ---------------------------------
__global__ __launch_bounds__(512, 1)
void k_stage2(const float* __restrict__ xv, const float* __restrict__ wr,
              const float* __restrict__ x, const int* __restrict__ ci,
              const float* __restrict__ we, const float* __restrict__ be,
              const float* __restrict__ ge, const float* __restrict__ bee,
              const float* __restrict__ me, const float* __restrict__ ve,
              const float* __restrict__ wS1, const float* __restrict__ bias1,
              float* __restrict__ em_out, float* __restrict__ bv1) {
    __shared__ float sxv[64], sq[64], sres[64], syv[64];
    __shared__ float sf[512], sem[512], ssm[512], sred[512];
    __shared__ float sv[512];
    __shared__ int   si[512];
    int b = blockIdx.x, t = threadIdx.x;
    int src = srcmap(b);
    const float* x1b = x + (size_t)src*C*N;
    const int* ci_b = ci + (size_t)src*N*K19;

    if (t < 64) sxv[t] = xv[b*O + t];
    __syncthreads();
    if (t < 64) {
        float a = 0.f;
        #pragma unroll 8
        for (int c = 0; c < C; ++c) a += wr[t*C + c]*sxv[c];
        sq[t] = a;
    }
    __syncthreads();
    {
        float a = 0.f;
        const float* p = x1b + t;
        #pragma unroll 8
        for (int c = 0; c < C; ++c) a += sq[c]*p[c*N];
        sf[t] = a * 0.125f;
    }
    __syncthreads();
    {
        float fk = sf[t];
        const int* ip = ci_b + (size_t)t*K19;
        #pragma unroll
        for (int k = 0; k < KC; ++k) fk += sf[ip[k]];
        sv[t] = fk; si[t] = t;
    }
    __syncthreads();
    for (int s = 256; s > 0; s >>= 1) {
        if (t < s) {
            float v2 = sv[t+s]; int i2 = si[t+s];
            if (v2 > sv[t] || (v2 == sv[t] && i2 < si[t])) { sv[t] = v2; si[t] = i2; }
        }
        __syncthreads();
    }
    int index = si[0];
    sem[t] = 1.f;
    __syncthreads();
    if (t < KC) sem[ci_b[(size_t)index*K19 + t]] = 0.f;
    if (t == KC) sem[index] = 0.f;
    __syncthreads();
    float s_ = sf[t] - (1.f - sem[t])*1e8f;
    sred[t] = s_;
    __syncthreads();
    for (int st = 256; st > 0; st >>= 1) {
        if (t < st) sred[t] = fmaxf(sred[t], sred[t+st]);
        __syncthreads();
    }
    float mxv = sred[0];
    __syncthreads();
    float e = expf(s_ - mxv);
    sred[t] = e;
    __syncthreads();
    for (int st = 256; st > 0; st >>= 1) {
        if (t < st) sred[t] += sred[t+st];
        __syncthreads();
    }
    float ssum = sred[0];
    __syncthreads();
    ssm[t] = e / ssum;
    __syncthreads();
    {
        int w = t >> 5, l = t & 31;
        #pragma unroll
        for (int u = 0; u < 4; ++u) {
            int c = w*4 + u;
            const float* p = x1b + (size_t)c*N;
            float s = 0.f;
            #pragma unroll
            for (int n0 = 0; n0 < 16; ++n0) { int n = n0*32 + l; s += p[n]*ssm[n]; }
            #pragma unroll
            for (int off = 16; off > 0; off >>= 1) s += __shfl_down_sync(~0u, s, off);
            if (l == 0) sres[c] = s;
        }
    }
    __syncthreads();
    if (t < 64) {
        float a = 0.f;
        #pragma unroll 8
        for (int c = 0; c < C; ++c) a += we[t*C + c]*sres[c];
        a += be[t];
        float sc = ge[t] / sqrtf(ve[t] + EPSBN);
        syv[t] = (a - me[t])*sc + bee[t];
    }
    __syncthreads();
    if (t < 64) {
        float a = bias1[t];
        #pragma unroll 8
        for (int c = 0; c < C; ++c) a += wS1[c*O + t]*syv[c];
        bv1[b*O + t] = a;
    }
    em_out[b*N + t] = sem[t];
}

// =============================================================================
extern "C" void kernel_launch(void* const* d_in, const int* in_sizes, int n_in,
                              void* d_out, int out_size) {
    const float* x        = (const float*)d_in[0];
    const float* w_reduce = (const float*)d_in[1];
    const float* w_erase  = (const float*)d_in[2];
    const float* b_erase  = (const float*)d_in[3];
    const float* g_erase  = (const float*)d_in[4];
    const float* be_erase = (const float*)d_in[5];
    const float* m_erase  = (const float*)d_in[6];
    const float* v_erase  = (const float*)d_in[7];
    const float* w0 = (const float*)d_in[8];
    const float* g0 = (const float*)d_in[9];
    const float* b0 = (const float*)d_in[10];
    const float* m0 = (const float*)d_in[11];
    const float* v0 = (const float*)d_in[12];
    const float* w1 = (const float*)d_in[13];
    const float* g1 = (const float*)d_in[14];
    const float* b1 = (const float*)d_in[15];
    const float* m1 = (const float*)d_in[16];
    const float* v1 = (const float*)d_in[17];
    float* out = (float*)d_out;

    float *p_xt, *p_cvh, *p_cv, *p_At0, *p_Dt0, *p_At1, *p_Dt1;
    float *p_em, *p_xv, *p_bv0, *p_bv1, *p_wAt, *p_wDt, *p_wS, *p_bias;
    int *p_cih, *p_ci, *p_idx;
    cudaGetSymbolAddress((void**)&p_xt,  g_xt);
    cudaGetSymbolAddress((void**)&p_cvh, g_cvh);
    cudaGetSymbolAddress((void**)&p_cih, g_cih);
    cudaGetSymbolAddress((void**)&p_cv,  g_cv);
    cudaGetSymbolAddress((void**)&p_ci,  g_ci);
    cudaGetSymbolAddress((void**)&p_At0, g_At0);
    cudaGetSymbolAddress((void**)&p_Dt0, g_Dt0);
    cudaGetSymbolAddress((void**)&p_At1, g_At1);
    cudaGetSymbolAddress((void**)&p_Dt1, g_Dt1);
    cudaGetSymbolAddress((void**)&p_em,  g_em);
    cudaGetSymbolAddress((void**)&p_xv,  g_xv);
    cudaGetSymbolAddress((void**)&p_bv0, g_bv0);
    cudaGetSymbolAddress((void**)&p_bv1, g_bv1);
    cudaGetSymbolAddress((void**)&p_wAt, g_wAt);
    cudaGetSymbolAddress((void**)&p_wDt, g_wDt);
    cudaGetSymbolAddress((void**)&p_wS,  g_wS);
    cudaGetSymbolAddress((void**)&p_bias,g_bias);
    cudaGetSymbolAddress((void**)&p_idx, g_idx);

    cudaFuncSetAttribute((const void*)knn19h, cudaFuncAttributeMaxDynamicSharedMemorySize, KNN_SMEM_BYTES);
    cudaFuncSetAttribute((const void*)k_edgepool<false>, cudaFuncAttributeMaxDynamicSharedMemorySize, EP_SMEM_BYTES);
    cudaFuncSetAttribute((const void*)k_edgepool<true>,  cudaFuncAttributeMaxDynamicSharedMemorySize, EP_SMEM_BYTES);

    k_prep_w<<<16, 256>>>(w0, g0, b0, m0, v0, p_wAt,       p_wDt,       p_wS,       p_bias);
    k_prep_w<<<16, 256>>>(w1, g1, b1, m1, v1, p_wAt + C*O, p_wDt + C*O, p_wS + C*O, p_bias + O);

    k_split<<<dim3(8, BATCH), 256>>>(x, p_xt);

    // K19 half-range scans (half table in smem, 3 blocks/SM), then exact merge
    knn19h<<<8*BATCH, 128, KNN_SMEM_BYTES>>>(p_xt, p_cvh, p_cih);
    k_merge19<<<BATCH, 512>>>(p_cvh, p_cih, p_cv, p_ci);

    k_stage1<<<BATCH, 512>>>(x, w_erase, b_erase, g_erase, be_erase, m_erase, v_erase,
                             p_wS, p_bias, p_bv0);

    k_gemm<<<dim3(8, BATCH), 256>>>(x, p_wAt,       p_wDt,       p_At0, p_Dt0, 0);
    k_gemm<<<dim3(8, BATCH), 256>>>(x, p_wAt + C*O, p_wDt + C*O, p_At1, p_Dt1, 1);

    // branch 0 (idx10 = first 10 of K19 cache, read in-place)
    k_edgepool<false><<<BATCH, 512, EP_SMEM_BYTES>>>(p_At0, p_Dt0, p_ci, nullptr, p_bv0,
                                                     out, p_xv, 0);

    // correlation / erase #2 (idx8 = first 8 of cache at src(b))
    k_stage2<<<BATCH, 512>>>(p_xv, w_reduce, x, p_ci,
                             w_erase, b_erase, g_erase, be_erase, m_erase, v_erase,
                             p_wS + C*O, p_bias + O, p_em, p_bv1);

    // branch-1 knn from cache at src(b) + mask
    k_patch<<<BATCH, 512>>>(p_xt, p_em, p_cv, p_ci, p_idx);

    // branch 1
    k_edgepool<true><<<BATCH, 512, EP_SMEM_BYTES>>>(p_At1, p_Dt1, p_idx, p_em, p_bv1,
                                                    out, nullptr, 1);
}